// round 1
// baseline (speedup 1.0000x reference)
#include <cuda_runtime.h>

// Problem constants
#define B_    4
#define C_    256
#define CE    128
#define W_    180
#define WS_   18
#define HW_   32400            // 180*180
#define NTOK  324              // 18*18
#define NWIN  400              // 4 * 10 * 10

#define K2_SMEM_BYTES ((128 * 336 + 64 * 129) * 4)   // 205056 B

// Scratch (device globals — no allocation allowed)
__device__ float g_E[(size_t)B_ * C_ * HW_];            // chan 0..127 = theta_e, 128..255 = phi_e ; layout (b, chan, hw)
__device__ float g_F[(size_t)NWIN * NTOK * NTOK];       // softmaxed attention
__device__ float g_Y[(size_t)B_ * C_ * HW_];            // y = F @ G, layout (b, c, hw)

__device__ __forceinline__ int hw_of(int ih, int iw, int n) {
    return (ih * WS_ + n / WS_) * W_ + iw * WS_ + n % WS_;
}

// ---------------------------------------------------------------------------
// Pointwise 1x1-conv GEMM: Out[(b,e,p)] = sum_c A[e][c] * Bsrc[(b,c,p)] (+resid)
// M=256 (2 tiles of 128), N=32400 per batch (254 tiles), K=256.
// A rows e<128 from Alo, e>=128 from Ahi (lets one kernel serve theta|phi stack
// and w_proj by passing Ahi = w_proj + 128*256).
// ---------------------------------------------------------------------------
__global__ __launch_bounds__(256) void k_pointwise(
    const float* __restrict__ Alo, const float* __restrict__ Ahi,
    const float* __restrict__ Bsrc, const float* __restrict__ resid,
    float* __restrict__ Out)
{
    __shared__ float As[8][132];   // [k][e]
    __shared__ float Bs[8][132];   // [k][p]
    const int b     = blockIdx.z;
    const int eBase = blockIdx.y * 128;
    const int pBase = blockIdx.x * 128;
    const int tid = threadIdx.x;
    const int tp = tid & 15;   // along p (coalesced epilogue)
    const int te = tid >> 4;   // along e
    const float* Bb = Bsrc + (size_t)b * C_ * HW_;

    float acc[8][8];
    #pragma unroll
    for (int i = 0; i < 8; i++)
        #pragma unroll
        for (int j = 0; j < 8; j++) acc[i][j] = 0.f;

    for (int k0 = 0; k0 < C_; k0 += 8) {
        #pragma unroll
        for (int l = 0; l < 4; l++) {
            int idx = tid + l * 256;
            int c_l = idx & 7;
            int e_l = idx >> 3;
            int e = eBase + e_l;
            int cg = k0 + c_l;
            As[c_l][e_l] = (e < CE) ? Alo[e * C_ + cg] : Ahi[(e - CE) * C_ + cg];
        }
        #pragma unroll
        for (int l = 0; l < 4; l++) {
            int idx = tid + l * 256;
            int p_l = idx & 127;
            int c_l = idx >> 7;
            int p = pBase + p_l;
            Bs[c_l][p_l] = (p < HW_) ? Bb[(size_t)(k0 + c_l) * HW_ + p] : 0.f;
        }
        __syncthreads();
        #pragma unroll
        for (int k = 0; k < 8; k++) {
            float a[8], bb[8];
            #pragma unroll
            for (int i = 0; i < 8; i++) a[i] = As[k][te * 8 + i];
            #pragma unroll
            for (int j = 0; j < 8; j++) bb[j] = Bs[k][tp * 8 + j];
            #pragma unroll
            for (int i = 0; i < 8; i++)
                #pragma unroll
                for (int j = 0; j < 8; j++) acc[i][j] += a[i] * bb[j];
        }
        __syncthreads();
    }

    #pragma unroll
    for (int i = 0; i < 8; i++) {
        int e = eBase + te * 8 + i;
        size_t row = ((size_t)b * C_ + e) * HW_;
        #pragma unroll
        for (int j = 0; j < 8; j++) {
            int p = pBase + tp * 8 + j;
            if (p < HW_) {
                float v = acc[i][j];
                if (resid) v += resid[row + p];
                Out[row + p] = v;
            }
        }
    }
}

// ---------------------------------------------------------------------------
// Attention scores + softmax per window.
// One CTA per window. Full phi (128 x 324, padded to 336 cols) in smem,
// theta in 64-row blocks. f kept in registers (4 rows x 21 strided cols per
// thread), softmax via 16-lane shfl reductions, result -> g_F.
// ---------------------------------------------------------------------------
__global__ __launch_bounds__(256, 1) void k_attn_softmax()
{
    extern __shared__ float smem[];
    float* sPh = smem;                  // [128][336], cols >=324 zero
    float* sTh = smem + 128 * 336;      // [64][129]
    const int w  = blockIdx.x;
    const int b  = w / 100;
    const int ih = (w / 10) % 10;
    const int iw = w % 10;
    const int tid = threadIdx.x;
    const int tx = tid & 15;
    const int ty = tid >> 4;
    const float* Eb = g_E + (size_t)b * C_ * HW_;

    for (int idx = tid; idx < 128 * 336; idx += 256) {
        int e = idx / 336;
        int m = idx - e * 336;
        float v = 0.f;
        if (m < NTOK) v = Eb[(size_t)(CE + e) * HW_ + hw_of(ih, iw, m)];
        sPh[idx] = v;
    }
    __syncthreads();

    const float sc = 0.08838834764831843f;   // 1/sqrt(128)
    const int nCols = (tx < 4) ? 21 : 20;    // cols m = tx + 16*j, m < 324

    for (int rb = 0; rb < 6; rb++) {
        int n0 = rb * 64;
        for (int idx = tid; idx < 64 * 128; idx += 256) {
            int e = idx >> 6;
            int r = idx & 63;
            int n = n0 + r;
            float v = 0.f;
            if (n < NTOK) v = Eb[(size_t)e * HW_ + hw_of(ih, iw, n)];
            sTh[r * 129 + e] = v;
        }
        __syncthreads();

        float acc[4][21];
        #pragma unroll
        for (int i = 0; i < 4; i++)
            #pragma unroll
            for (int j = 0; j < 21; j++) acc[i][j] = 0.f;

        for (int e = 0; e < 128; e++) {
            float t0 = sTh[ty * 129 + e];
            float t1 = sTh[(ty + 16) * 129 + e];
            float t2 = sTh[(ty + 32) * 129 + e];
            float t3 = sTh[(ty + 48) * 129 + e];
            const float* pr = sPh + e * 336 + tx;
            #pragma unroll
            for (int j = 0; j < 21; j++) {
                float p = pr[16 * j];
                acc[0][j] += t0 * p;
                acc[1][j] += t1 * p;
                acc[2][j] += t2 * p;
                acc[3][j] += t3 * p;
            }
        }

        #pragma unroll
        for (int i = 0; i < 4; i++) {
            int n = n0 + ty + 16 * i;
            float mx = -1e30f;
            #pragma unroll
            for (int j = 0; j < 21; j++)
                if (j < nCols) mx = fmaxf(mx, acc[i][j] * sc);
            #pragma unroll
            for (int off = 8; off >= 1; off >>= 1)
                mx = fmaxf(mx, __shfl_xor_sync(0xffffffffu, mx, off));
            float s = 0.f;
            #pragma unroll
            for (int j = 0; j < 21; j++)
                if (j < nCols) { float ev = __expf(acc[i][j] * sc - mx); acc[i][j] = ev; s += ev; }
            #pragma unroll
            for (int off = 8; off >= 1; off >>= 1)
                s += __shfl_xor_sync(0xffffffffu, s, off);
            float inv = 1.f / s;
            if (n < NTOK) {
                float* Fr = g_F + ((size_t)w * NTOK + n) * NTOK + tx;
                #pragma unroll
                for (int j = 0; j < 21; j++)
                    if (j < nCols) Fr[16 * j] = acc[i][j] * inv;
            }
        }
        __syncthreads();
    }
}

// ---------------------------------------------------------------------------
// y = F @ G per window: (324x324)@(324x256). BM=BN=128, BK=8, 8x8 microtile.
// G[m][c] gathered from x, output to g_Y in (b,c,hw) layout.
// ---------------------------------------------------------------------------
__global__ __launch_bounds__(256) void k_attn_v(const float* __restrict__ x)
{
    __shared__ float As[8][132];   // [m][n]  (F tile)
    __shared__ float Bs[8][132];   // [m][c]  (G tile)
    const int w  = blockIdx.z;
    const int b  = w / 100;
    const int ih = (w / 10) % 10;
    const int iw = w % 10;
    const int nBase = blockIdx.y * 128;   // 0,128,256
    const int cBase = blockIdx.x * 128;   // 0,128
    const int tid = threadIdx.x;
    const int tm = tid & 15;   // along n (coalesced writes)
    const int tn = tid >> 4;   // along c
    const float* Fw = g_F + (size_t)w * NTOK * NTOK;
    const float* xb = x + (size_t)b * C_ * HW_;

    float acc[8][8];
    #pragma unroll
    for (int i = 0; i < 8; i++)
        #pragma unroll
        for (int j = 0; j < 8; j++) acc[i][j] = 0.f;

    for (int k0 = 0; k0 < NTOK; k0 += 8) {
        #pragma unroll
        for (int l = 0; l < 4; l++) {
            int idx = tid + l * 256;
            int m_l = idx & 7;
            int n_l = idx >> 3;
            int n = nBase + n_l;
            int mg = k0 + m_l;
            As[m_l][n_l] = (n < NTOK && mg < NTOK) ? Fw[(size_t)n * NTOK + mg] : 0.f;
        }
        #pragma unroll
        for (int l = 0; l < 4; l++) {
            int idx = tid + l * 256;
            int m_l = idx & 7;
            int c_l = idx >> 3;
            int mg = k0 + m_l;
            float v = 0.f;
            if (mg < NTOK) v = xb[(size_t)(cBase + c_l) * HW_ + hw_of(ih, iw, mg)];
            Bs[m_l][c_l] = v;
        }
        __syncthreads();
        #pragma unroll
        for (int k = 0; k < 8; k++) {
            float a[8], g[8];
            #pragma unroll
            for (int i = 0; i < 8; i++) a[i] = As[k][tm * 8 + i];
            #pragma unroll
            for (int j = 0; j < 8; j++) g[j] = Bs[k][tn * 8 + j];
            #pragma unroll
            for (int i = 0; i < 8; i++)
                #pragma unroll
                for (int j = 0; j < 8; j++) acc[i][j] += a[i] * g[j];
        }
        __syncthreads();
    }

    int hwN[8]; bool vN[8];
    #pragma unroll
    for (int i = 0; i < 8; i++) {
        int n = nBase + tm * 8 + i;
        vN[i] = (n < NTOK);
        hwN[i] = vN[i] ? hw_of(ih, iw, n) : 0;
    }
    #pragma unroll
    for (int j = 0; j < 8; j++) {
        int c = cBase + tn * 8 + j;
        float* yr = g_Y + ((size_t)b * C_ + c) * HW_;
        #pragma unroll
        for (int i = 0; i < 8; i++)
            if (vN[i]) yr[hwN[i]] = acc[i][j];
    }
}

// ---------------------------------------------------------------------------
extern "C" void kernel_launch(void* const* d_in, const int* in_sizes, int n_in,
                              void* d_out, int out_size)
{
    const float* x       = (const float*)d_in[0];
    const float* w_theta = (const float*)d_in[1];
    const float* w_phi   = (const float*)d_in[2];
    const float* w_proj  = (const float*)d_in[3];
    float* out = (float*)d_out;

    void* pE = nullptr;
    void* pY = nullptr;
    cudaGetSymbolAddress(&pE, g_E);
    cudaGetSymbolAddress(&pY, g_Y);

    cudaFuncSetAttribute(k_attn_softmax,
                         cudaFuncAttributeMaxDynamicSharedMemorySize,
                         K2_SMEM_BYTES);

    dim3 gp((HW_ + 127) / 128, 2, B_);   // (254, 2, 4)

    // 1) embeddings: theta/phi = [w_theta; w_phi] @ x
    k_pointwise<<<gp, 256>>>(w_theta, w_phi, x, nullptr, (float*)pE);
    // 2) f = softmax(theta^T phi / sqrt(Ce)) per window
    k_attn_softmax<<<NWIN, 256, K2_SMEM_BYTES>>>();
    // 3) y = f @ g per window
    dim3 gv(2, 3, NWIN);
    k_attn_v<<<gv, 256>>>(x);
    // 4) out = x + w_proj @ y
    k_pointwise<<<gp, 256>>>(w_proj, w_proj + CE * C_, (const float*)pY, x, out);
}

// round 3
// speedup vs baseline: 1.9740x; 1.9740x over previous
#include <cuda_runtime.h>
#include <cstdint>

#define B_    4
#define C_    256
#define CE    128
#define W_    180
#define WS_   18
#define HW_   32400
#define NTOK  324
#define NWIN  400

// Scratch (device globals — no allocation allowed)
__device__ float g_E[(size_t)B_ * C_ * HW_];       // rows 0..127 theta, 128..255 phi; (b,chan,hw)
__device__ float g_F[(size_t)NWIN * NTOK * NTOK];  // F transposed: [w][m(key)][n(query)]
__device__ float g_Y[(size_t)B_ * C_ * HW_];       // y, (b,c,hw)

__device__ __forceinline__ int hw_of(int ih, int iw, int n) {
    return (ih * WS_ + n / WS_) * W_ + iw * WS_ + n % WS_;
}
__device__ __forceinline__ float to_tf32(float x) {
    uint32_t r; asm("cvt.rna.tf32.f32 %0, %1;" : "=r"(r) : "f"(x));
    return __uint_as_float(r);
}
__device__ __forceinline__ void mma8(float* d, const uint32_t* a, const uint32_t* b) {
    asm volatile("mma.sync.aligned.m16n8k8.row.col.f32.tf32.tf32.f32 "
        "{%0,%1,%2,%3}, {%4,%5,%6,%7}, {%8,%9}, {%0,%1,%2,%3};"
        : "+f"(d[0]), "+f"(d[1]), "+f"(d[2]), "+f"(d[3])
        : "r"(a[0]), "r"(a[1]), "r"(a[2]), "r"(a[3]), "r"(b[0]), "r"(b[1]));
}

// ---------------------------------------------------------------------------
// Pointwise 1x1-conv GEMM (tf32 tensor cores):
// Out[(b,e,p)] = sum_c A[e][c] * Bsrc[(b,c,p)] (+resid). M=256,N=32400/b,K=256
// Tiles: BM=128, BN=128, BK=16. 8 warps, each 64x32 (4x4 m16n8k8 tiles).
// ---------------------------------------------------------------------------
__global__ __launch_bounds__(256, 2) void k_pw(
    const float* __restrict__ Alo, const float* __restrict__ Ahi,
    const float* __restrict__ Bsrc, const float* __restrict__ resid,
    float* __restrict__ Out)
{
    __shared__ float As[128][20];   // [m=e][k] pad20 -> conflict-free frag loads
    __shared__ float Bs[16][136];   // [k][n=p] pad136 -> conflict-free frag loads
    const int b = blockIdx.z, eBase = blockIdx.y * 128, pBase = blockIdx.x * 128;
    const int tid = threadIdx.x, lane = tid & 31, wid = tid >> 5;
    const int wm = (wid >> 2) * 64, wn = (wid & 3) * 32;
    const int gr = lane >> 2, gc = lane & 3;
    const float* Bb = Bsrc + (size_t)b * C_ * HW_;

    float acc[4][4][4] = {};

    for (int k0 = 0; k0 < C_; k0 += 16) {
        #pragma unroll
        for (int l = 0; l < 8; l++) {
            int idx = tid + l * 256;
            int k = idx & 15, e_l = idx >> 4;
            int e = eBase + e_l;
            float v = (e < CE) ? Alo[e * C_ + k0 + k] : Ahi[(e - CE) * C_ + k0 + k];
            As[e_l][k] = to_tf32(v);
        }
        #pragma unroll
        for (int l = 0; l < 8; l++) {
            int idx = tid + l * 256;
            int p_l = idx & 127, k = idx >> 7;
            int p = pBase + p_l;
            Bs[k][p_l] = (p < HW_) ? to_tf32(Bb[(size_t)(k0 + k) * HW_ + p]) : 0.f;
        }
        __syncthreads();
        #pragma unroll
        for (int kk = 0; kk < 16; kk += 8) {
            uint32_t a[4][4], bf[4][2];
            #pragma unroll
            for (int mt = 0; mt < 4; mt++) {
                int r0 = wm + mt * 16 + gr;
                a[mt][0] = __float_as_uint(As[r0][kk + gc]);
                a[mt][1] = __float_as_uint(As[r0 + 8][kk + gc]);
                a[mt][2] = __float_as_uint(As[r0][kk + gc + 4]);
                a[mt][3] = __float_as_uint(As[r0 + 8][kk + gc + 4]);
            }
            #pragma unroll
            for (int nt = 0; nt < 4; nt++) {
                bf[nt][0] = __float_as_uint(Bs[kk + gc][wn + nt * 8 + gr]);
                bf[nt][1] = __float_as_uint(Bs[kk + gc + 4][wn + nt * 8 + gr]);
            }
            #pragma unroll
            for (int mt = 0; mt < 4; mt++)
                #pragma unroll
                for (int nt = 0; nt < 4; nt++)
                    mma8(acc[mt][nt], a[mt], bf[nt]);
        }
        __syncthreads();
    }

    #pragma unroll
    for (int mt = 0; mt < 4; mt++) {
        #pragma unroll
        for (int half = 0; half < 2; half++) {
            int e = eBase + wm + mt * 16 + gr + half * 8;
            size_t rowb = ((size_t)b * C_ + e) * HW_;
            #pragma unroll
            for (int nt = 0; nt < 4; nt++) {
                int p = pBase + wn + nt * 8 + 2 * gc;
                if (p < HW_) {
                    float v0 = acc[mt][nt][half * 2 + 0];
                    float v1 = acc[mt][nt][half * 2 + 1];
                    if (resid) {
                        float2 r = *(const float2*)&resid[rowb + p];
                        v0 += r.x; v1 += r.y;
                    }
                    *(float2*)&Out[rowb + p] = make_float2(v0, v1);
                }
            }
        }
    }
}

// ---------------------------------------------------------------------------
// K2: per-window transposed scores + column softmax.
// S_t[m][n] = sum_e phi[e][m] * theta[e][n]; F_t[m][n] = softmax over m.
// CTA: one window x 64 query cols. Full phi (384x132 tf32) in smem.
// 8 warps each own 48 m-rows (3 m-tiles) x 8 n-tiles. Sum-only softmax
// (logits tiny: |logit| < ~0.2), cross-warp reduce via smem.
// ---------------------------------------------------------------------------
#define K2_SMEM ((384 * 132 + 16 * 72 + 8 * 64 + 64) * 4)

__global__ __launch_bounds__(256, 1) void k_attn()
{
    extern __shared__ float sm[];
    float* sPh  = sm;                       // [384][132]  phi^T as [m][e]
    float* sTh  = sm + 384 * 132;           // [16][72]    theta slice [e][n]
    float* sRed = sTh + 16 * 72;            // [8][64]     per-warp partial sums
    float* sInv = sRed + 8 * 64;            // [64]        1/colsum

    const int w = blockIdx.y;
    const int nBase = blockIdx.x * 64;
    const int b = w / 100, ih = (w / 10) % 10, iw = w % 10;
    const int tid = threadIdx.x, lane = tid & 31, wid = tid >> 5;
    const int gr = lane >> 2, gc = lane & 3;
    const int wm = wid * 48;
    const float* Eb = g_E + (size_t)b * C_ * HW_;

    // Load phi: sPh[m][e] <- E[CE+e][hw(m)], m<324 else 0. 64 m x 4 e per pass.
    {
        int m = tid & 63, e0 = tid >> 6;
        for (int mb = 0; mb < 384; mb += 64) {
            int mg = mb + m;
            int hw = (mg < NTOK) ? hw_of(ih, iw, mg) : 0;
            bool v = (mg < NTOK);
            for (int e = e0; e < 128; e += 4)
                sPh[mg * 132 + e] = v ? to_tf32(Eb[(size_t)(CE + e) * HW_ + hw]) : 0.f;
        }
    }
    __syncthreads();

    float acc[3][8][4] = {};

    for (int k0 = 0; k0 < 128; k0 += 16) {
        // theta slice: sTh[e][n] <- E[k0+e][hw(nBase+n)]
        #pragma unroll
        for (int l = 0; l < 4; l++) {
            int n = tid & 63, e_l = (tid >> 6) + l * 4;
            int ng = nBase + n;
            sTh[e_l * 72 + n] = (ng < NTOK)
                ? to_tf32(Eb[(size_t)(k0 + e_l) * HW_ + hw_of(ih, iw, ng)]) : 0.f;
        }
        __syncthreads();
        #pragma unroll
        for (int kk = 0; kk < 16; kk += 8) {
            uint32_t a[3][4], bf[8][2];
            #pragma unroll
            for (int mt = 0; mt < 3; mt++) {
                int r0 = wm + mt * 16 + gr;
                int kc = k0 + kk + gc;
                a[mt][0] = __float_as_uint(sPh[r0 * 132 + kc]);
                a[mt][1] = __float_as_uint(sPh[(r0 + 8) * 132 + kc]);
                a[mt][2] = __float_as_uint(sPh[r0 * 132 + kc + 4]);
                a[mt][3] = __float_as_uint(sPh[(r0 + 8) * 132 + kc + 4]);
            }
            #pragma unroll
            for (int nt = 0; nt < 8; nt++) {
                bf[nt][0] = __float_as_uint(sTh[(kk + gc) * 72 + nt * 8 + gr]);
                bf[nt][1] = __float_as_uint(sTh[(kk + gc + 4) * 72 + nt * 8 + gr]);
            }
            #pragma unroll
            for (int mt = 0; mt < 3; mt++)
                #pragma unroll
                for (int nt = 0; nt < 8; nt++)
                    mma8(acc[mt][nt], a[mt], bf[nt]);
        }
        __syncthreads();
    }

    // exp (no max-sub: logits tiny), mask invalid m rows
    const float sc = 0.08838834764831843f;  // 1/sqrt(128)
    #pragma unroll
    for (int mt = 0; mt < 3; mt++) {
        int m0 = wm + mt * 16 + gr;
        bool v0 = (m0 < NTOK), v1 = (m0 + 8 < NTOK);
        #pragma unroll
        for (int nt = 0; nt < 8; nt++) {
            acc[mt][nt][0] = v0 ? __expf(acc[mt][nt][0] * sc) : 0.f;
            acc[mt][nt][1] = v0 ? __expf(acc[mt][nt][1] * sc) : 0.f;
            acc[mt][nt][2] = v1 ? __expf(acc[mt][nt][2] * sc) : 0.f;
            acc[mt][nt][3] = v1 ? __expf(acc[mt][nt][3] * sc) : 0.f;
        }
    }

    // column sums: local over m-tiles, shfl over gr (lanes stride 4), smem over warps
    float ls[8][2];
    #pragma unroll
    for (int nt = 0; nt < 8; nt++) {
        ls[nt][0] = ls[nt][1] = 0.f;
        #pragma unroll
        for (int mt = 0; mt < 3; mt++) {
            ls[nt][0] += acc[mt][nt][0] + acc[mt][nt][2];
            ls[nt][1] += acc[mt][nt][1] + acc[mt][nt][3];
        }
        #pragma unroll
        for (int off = 4; off < 32; off <<= 1) {
            ls[nt][0] += __shfl_xor_sync(0xffffffffu, ls[nt][0], off);
            ls[nt][1] += __shfl_xor_sync(0xffffffffu, ls[nt][1], off);
        }
    }
    if (gr == 0) {
        #pragma unroll
        for (int nt = 0; nt < 8; nt++) {
            sRed[wid * 64 + nt * 8 + 2 * gc]     = ls[nt][0];
            sRed[wid * 64 + nt * 8 + 2 * gc + 1] = ls[nt][1];
        }
    }
    __syncthreads();
    if (tid < 64) {
        float s = 0.f;
        #pragma unroll
        for (int ww = 0; ww < 8; ww++) s += sRed[ww * 64 + tid];
        sInv[tid] = 1.f / s;
    }
    __syncthreads();

    // store F_t[m][n] (float2 along n)
    float* Fw = g_F + (size_t)w * NTOK * NTOK;
    #pragma unroll
    for (int nt = 0; nt < 8; nt++) {
        int nl = nt * 8 + 2 * gc;
        int ng = nBase + nl;
        if (ng < NTOK) {
            float inv0 = sInv[nl], inv1 = sInv[nl + 1];
            #pragma unroll
            for (int mt = 0; mt < 3; mt++) {
                int m0 = wm + mt * 16 + gr;
                if (m0 < NTOK)
                    *(float2*)&Fw[(size_t)m0 * NTOK + ng] =
                        make_float2(acc[mt][nt][0] * inv0, acc[mt][nt][1] * inv1);
                if (m0 + 8 < NTOK)
                    *(float2*)&Fw[(size_t)(m0 + 8) * NTOK + ng] =
                        make_float2(acc[mt][nt][2] * inv0, acc[mt][nt][3] * inv1);
            }
        }
    }
}

// ---------------------------------------------------------------------------
// K3: Y^T = G^T @ F_t per window. M=c=256, N=n=324, K=m=324.
// A[c][m] gathered from x (coalesced along m), B=F_t[m][n] (coalesced along n).
// Output written straight into (b,c,hw) layout.
// ---------------------------------------------------------------------------
__global__ __launch_bounds__(256, 2) void k_av(const float* __restrict__ x)
{
    __shared__ float As[128][20];   // [c][m]
    __shared__ float Bs[16][136];   // [m][n]
    const int w = blockIdx.z, cBase = blockIdx.y * 128, nBase = blockIdx.x * 128;
    const int b = w / 100, ih = (w / 10) % 10, iw = w % 10;
    const int tid = threadIdx.x, lane = tid & 31, wid = tid >> 5;
    const int wm = (wid >> 2) * 64, wn = (wid & 3) * 32;
    const int gr = lane >> 2, gc = lane & 3;
    const float* xb = x + (size_t)b * C_ * HW_;
    const float* Fw = g_F + (size_t)w * NTOK * NTOK;

    float acc[4][4][4] = {};

    for (int k0 = 0; k0 < NTOK; k0 += 16) {
        #pragma unroll
        for (int l = 0; l < 8; l++) {
            int idx = tid + l * 256;
            int m_l = idx & 15, c_l = idx >> 4;
            int m = k0 + m_l;
            As[c_l][m_l] = (m < NTOK)
                ? to_tf32(xb[(size_t)(cBase + c_l) * HW_ + hw_of(ih, iw, m)]) : 0.f;
        }
        #pragma unroll
        for (int l = 0; l < 8; l++) {
            int idx = tid + l * 256;
            int n_l = idx & 127, m_l = idx >> 7;
            int m = k0 + m_l, n = nBase + n_l;
            Bs[m_l][n_l] = (m < NTOK && n < NTOK)
                ? to_tf32(Fw[(size_t)m * NTOK + n]) : 0.f;
        }
        __syncthreads();
        #pragma unroll
        for (int kk = 0; kk < 16; kk += 8) {
            uint32_t a[4][4], bf[4][2];
            #pragma unroll
            for (int mt = 0; mt < 4; mt++) {
                int r0 = wm + mt * 16 + gr;
                a[mt][0] = __float_as_uint(As[r0][kk + gc]);
                a[mt][1] = __float_as_uint(As[r0 + 8][kk + gc]);
                a[mt][2] = __float_as_uint(As[r0][kk + gc + 4]);
                a[mt][3] = __float_as_uint(As[r0 + 8][kk + gc + 4]);
            }
            #pragma unroll
            for (int nt = 0; nt < 4; nt++) {
                bf[nt][0] = __float_as_uint(Bs[kk + gc][wn + nt * 8 + gr]);
                bf[nt][1] = __float_as_uint(Bs[kk + gc + 4][wn + nt * 8 + gr]);
            }
            #pragma unroll
            for (int mt = 0; mt < 4; mt++)
                #pragma unroll
                for (int nt = 0; nt < 4; nt++)
                    mma8(acc[mt][nt], a[mt], bf[nt]);
        }
        __syncthreads();
    }

    #pragma unroll
    for (int nt = 0; nt < 4; nt++) {
        int n = nBase + wn + nt * 8 + 2 * gc;
        if (n < NTOK) {
            int hw0 = hw_of(ih, iw, n);
            int hw1 = hw_of(ih, iw, n + 1);
            #pragma unroll
            for (int mt = 0; mt < 4; mt++) {
                #pragma unroll
                for (int half = 0; half < 2; half++) {
                    int c = cBase + wm + mt * 16 + gr + half * 8;
                    float* yr = g_Y + ((size_t)b * C_ + c) * HW_;
                    yr[hw0] = acc[mt][nt][half * 2 + 0];
                    yr[hw1] = acc[mt][nt][half * 2 + 1];
                }
            }
        }
    }
}

// ---------------------------------------------------------------------------
extern "C" void kernel_launch(void* const* d_in, const int* in_sizes, int n_in,
                              void* d_out, int out_size)
{
    const float* x       = (const float*)d_in[0];
    const float* w_theta = (const float*)d_in[1];
    const float* w_phi   = (const float*)d_in[2];
    const float* w_proj  = (const float*)d_in[3];
    float* out = (float*)d_out;

    void* pE = nullptr;
    void* pY = nullptr;
    cudaGetSymbolAddress(&pE, g_E);
    cudaGetSymbolAddress(&pY, g_Y);

    cudaFuncSetAttribute(k_attn, cudaFuncAttributeMaxDynamicSharedMemorySize, K2_SMEM);

    dim3 gp((HW_ + 127) / 128, 2, B_);   // (254, 2, 4)

    // 1) embeddings: [theta; phi] = [w_theta; w_phi] @ x
    k_pw<<<gp, 256>>>(w_theta, w_phi, x, nullptr, (float*)pE);
    // 2) F_t = softmax_m(phi^T theta / sqrt(Ce)) per window
    dim3 ga(6, NWIN);
    k_attn<<<ga, 256, K2_SMEM>>>();
    // 3) Y^T = G^T F_t per window
    dim3 gv(3, 2, NWIN);
    k_av<<<gv, 256>>>(x);
    // 4) out = x + w_proj @ y
    k_pw<<<gp, 256>>>(w_proj, w_proj + CE * C_, (const float*)pY, x, out);
}

// round 4
// speedup vs baseline: 3.3154x; 1.6796x over previous
#include <cuda_runtime.h>
#include <cstdint>

#define B_    4
#define C_    256
#define CE    128
#define W_    180
#define WS_   18
#define HW_   32400
#define NTOK  324
#define NWIN  400
#define MPAD  336   // padded tokens-per-window stride

// Scratch (device globals — no allocation allowed)
__device__ float g_Ew[(size_t)NWIN * C_ * MPAD];  // [w][chan][m] chan0..127 theta, 128..255 phi
__device__ float g_Yw[(size_t)NWIN * C_ * MPAD];  // [w][c][n]

__device__ __forceinline__ void mma8(float* d, const uint32_t* a, const uint32_t* b) {
    asm volatile("mma.sync.aligned.m16n8k8.row.col.f32.tf32.tf32.f32 "
        "{%0,%1,%2,%3}, {%4,%5,%6,%7}, {%8,%9}, {%0,%1,%2,%3};"
        : "+f"(d[0]), "+f"(d[1]), "+f"(d[2]), "+f"(d[3])
        : "r"(a[0]), "r"(a[1]), "r"(a[2]), "r"(a[3]), "r"(b[0]), "r"(b[1]));
}
__device__ __forceinline__ uint32_t fu(float x) { return __float_as_uint(x); }

// ---------------------------------------------------------------------------
// k_pw<MODE>: Out[e][p] = sum_c A[e][c] * B[c][p] over full image.
// MODE 0: B = x flat, out -> Ew windowed (no resid).
// MODE 1: B = Yw windowed (gather), out -> flat + resid.
// BM=128 BN=128 BK=16, 8 warps x (64x32), register-staged prefetch pipeline.
// ---------------------------------------------------------------------------
template<int MODE>
__global__ __launch_bounds__(256, 2) void k_pw(
    const float* __restrict__ Alo, const float* __restrict__ Ahi,
    const float* __restrict__ Bsrc, const float* __restrict__ resid,
    float* __restrict__ Out)
{
    __shared__ float As[128][20];
    __shared__ float Bs[16][136];
    __shared__ int   sOff[128];     // MODE 1: window base offsets per p
    const int b = blockIdx.z, eBase = blockIdx.y * 128, pBase = blockIdx.x * 128;
    const int tid = threadIdx.x, lane = tid & 31, wid = tid >> 5;
    const int wm = (wid >> 2) * 64, wn = (wid & 3) * 32;
    const int gr = lane >> 2, gc = lane & 3;
    const float* Bb = Bsrc + (MODE == 0 ? (size_t)b * C_ * HW_ : 0);

    if (MODE == 1 && tid < 128) {
        int p = pBase + tid;
        int off = 0;
        if (p < HW_) {
            int gh = p / W_, gw = p - gh * W_;
            int w = b * 100 + (gh / WS_) * 10 + gw / WS_;
            int m = (gh % WS_) * WS_ + gw % WS_;
            off = w * (C_ * MPAD) + m;
        }
        sOff[tid] = off;
    }
    if (MODE == 1) __syncthreads();

    float acc[4][4][4] = {};
    float aR[8], bR[8];

    // staged loads for k0
    auto loadA = [&](int k0) {
        #pragma unroll
        for (int l = 0; l < 8; l++) {
            int idx = tid + l * 256;
            int k = idx & 15, e_l = idx >> 4;
            int e = eBase + e_l;
            aR[l] = (e < CE) ? Alo[e * C_ + k0 + k] : Ahi[(e - CE) * C_ + k0 + k];
        }
    };
    auto loadB = [&](int k0) {
        #pragma unroll
        for (int l = 0; l < 8; l++) {
            int idx = tid + l * 256;
            int p_l = idx & 127, k = idx >> 7;
            int p = pBase + p_l;
            if (MODE == 0)
                bR[l] = (p < HW_) ? Bb[(size_t)(k0 + k) * HW_ + p] : 0.f;
            else
                bR[l] = (p < HW_) ? Bb[(size_t)sOff[p_l] + (size_t)(k0 + k) * MPAD] : 0.f;
        }
    };

    loadA(0); loadB(0);
    for (int it = 0; it < 16; it++) {
        #pragma unroll
        for (int l = 0; l < 8; l++) {
            int idx = tid + l * 256;
            As[idx >> 4][idx & 15] = aR[l];
        }
        #pragma unroll
        for (int l = 0; l < 8; l++) {
            int idx = tid + l * 256;
            Bs[idx >> 7][idx & 127] = bR[l];
        }
        __syncthreads();
        if (it < 15) { loadA((it + 1) * 16); loadB((it + 1) * 16); }
        #pragma unroll
        for (int kk = 0; kk < 16; kk += 8) {
            uint32_t a[4][4], bf[4][2];
            #pragma unroll
            for (int mt = 0; mt < 4; mt++) {
                int r0 = wm + mt * 16 + gr;
                a[mt][0] = fu(As[r0][kk + gc]);
                a[mt][1] = fu(As[r0 + 8][kk + gc]);
                a[mt][2] = fu(As[r0][kk + gc + 4]);
                a[mt][3] = fu(As[r0 + 8][kk + gc + 4]);
            }
            #pragma unroll
            for (int nt = 0; nt < 4; nt++) {
                bf[nt][0] = fu(Bs[kk + gc][wn + nt * 8 + gr]);
                bf[nt][1] = fu(Bs[kk + gc + 4][wn + nt * 8 + gr]);
            }
            #pragma unroll
            for (int mt = 0; mt < 4; mt++)
                #pragma unroll
                for (int nt = 0; nt < 4; nt++)
                    mma8(acc[mt][nt], a[mt], bf[nt]);
        }
        __syncthreads();
    }

    // epilogue
    #pragma unroll
    for (int nt = 0; nt < 4; nt++) {
        int p = pBase + wn + nt * 8 + 2 * gc;
        if (p >= HW_) continue;
        if (MODE == 0) {
            int gh = p / W_, gw = p - gh * W_;
            int w = b * 100 + (gh / WS_) * 10 + gw / WS_;
            int m = (gh % WS_) * WS_ + gw % WS_;
            size_t rowOff = (size_t)w * (C_ * MPAD) + m;
            #pragma unroll
            for (int mt = 0; mt < 4; mt++)
                #pragma unroll
                for (int half = 0; half < 2; half++) {
                    int e = eBase + wm + mt * 16 + gr + half * 8;
                    *(float2*)&Out[rowOff + (size_t)e * MPAD] =
                        make_float2(acc[mt][nt][half * 2], acc[mt][nt][half * 2 + 1]);
                }
        } else {
            #pragma unroll
            for (int mt = 0; mt < 4; mt++)
                #pragma unroll
                for (int half = 0; half < 2; half++) {
                    int e = eBase + wm + mt * 16 + gr + half * 8;
                    size_t rowb = ((size_t)b * C_ + e) * HW_;
                    float2 r = *(const float2*)&resid[rowb + p];
                    *(float2*)&Out[rowb + p] =
                        make_float2(acc[mt][nt][half * 2] + r.x,
                                    acc[mt][nt][half * 2 + 1] + r.y);
                }
        }
    }
}

// ---------------------------------------------------------------------------
// Fused attention: per (window, 64-query tile).
// Loop m-tiles of 32: S~[m][n] = exp(sc * sum_e phi[e][m] theta[e][n]) (masked),
// accumulate colsum, Y[c][n] += G[c][m] S~[m][n]; scale Y by 1/colsum at end.
// smem ~106KB -> 2 CTAs/SM.
// ---------------------------------------------------------------------------
#define K2_SMEM ((128*72 + 128*40 + 256*40 + 32*72 + 64 + 64) * 4)

__global__ __launch_bounds__(256, 2) void k_fattn(const float* __restrict__ x)
{
    extern __shared__ float sm[];
    float* sTh  = sm;                    // [128 e][72]  theta (n-tile)
    float* sPhi = sTh + 128 * 72;        // [128 e][40]  phi (m-tile)
    float* sG   = sPhi + 128 * 40;       // [256 c][40]  G (m-tile)
    float* sF   = sG + 256 * 40;         // [32 m][72]   exp(S) tile
    float* sSum = sF + 32 * 72;          // [64]
    float* sInv = sSum + 64;             // [64]

    const int w = blockIdx.y, nBase = blockIdx.x * 64;
    const int b = w / 100, ih = (w / 10) % 10, iw = w % 10;
    const int tid = threadIdx.x, lane = tid & 31, wid = tid >> 5;
    const int gr = lane >> 2, gc = lane & 3;
    // S warp layout: 2(m)x4(n); Y warp layout: 4(c)x2(n)
    const int wm2 = (wid >> 2) * 16, wn2 = (wid & 3) * 16;
    const int wc = (wid >> 1) * 64, wn3 = (wid & 1) * 32;
    const float* Ew = g_Ew + (size_t)w * C_ * MPAD;
    const float* xb = x + (size_t)b * C_ * HW_;
    const int hwBase = (ih * WS_) * W_ + iw * WS_;
    const float sc = 0.08838834764831843f;  // 1/sqrt(128)

    // theta: sTh[e][n]
    #pragma unroll
    for (int l = 0; l < 32; l++) {
        int idx = tid + l * 256;
        int e = idx >> 6, n = idx & 63;
        int ng = nBase + n;
        sTh[e * 72 + n] = (ng < NTOK) ? Ew[(size_t)e * MPAD + ng] : 0.f;
    }
    if (tid < 64) sSum[tid] = 0.f;
    __syncthreads();

    float yacc[4][4][4] = {};
    float colp[4] = {};

    for (int mi = 0; mi < 11; mi++) {
        int m0 = mi * 32;
        // phi tile: sPhi[e][mrel]
        #pragma unroll
        for (int l = 0; l < 16; l++) {
            int idx = tid + l * 256;
            int e = idx >> 5, mrel = idx & 31;
            int mg = m0 + mrel;
            sPhi[e * 40 + mrel] = (mg < NTOK) ? Ew[(size_t)(CE + e) * MPAD + mg] : 0.f;
        }
        // G tile: sG[c][mrel]
        #pragma unroll
        for (int l = 0; l < 32; l++) {
            int idx = tid + l * 256;
            int c = idx >> 5, mrel = idx & 31;
            int mg = m0 + mrel;
            float v = 0.f;
            if (mg < NTOK) {
                int hw = hwBase + (mg / WS_) * W_ + mg % WS_;
                v = xb[(size_t)c * HW_ + hw];
            }
            sG[c * 40 + mrel] = v;
        }
        __syncthreads();

        // S GEMM: warp 16m x 16n, K=128
        float s[2][4] = {};
        #pragma unroll
        for (int kk = 0; kk < 128; kk += 8) {
            uint32_t a[4], bf[2][2];
            a[0] = fu(sPhi[(kk + gc) * 40 + wm2 + gr]);
            a[1] = fu(sPhi[(kk + gc) * 40 + wm2 + gr + 8]);
            a[2] = fu(sPhi[(kk + gc + 4) * 40 + wm2 + gr]);
            a[3] = fu(sPhi[(kk + gc + 4) * 40 + wm2 + gr + 8]);
            #pragma unroll
            for (int nt = 0; nt < 2; nt++) {
                bf[nt][0] = fu(sTh[(kk + gc) * 72 + wn2 + nt * 8 + gr]);
                bf[nt][1] = fu(sTh[(kk + gc + 4) * 72 + wn2 + nt * 8 + gr]);
            }
            #pragma unroll
            for (int nt = 0; nt < 2; nt++)
                mma8(s[nt], a, bf[nt]);
        }

        // exp + mask + store sF + colsum partials
        int mA = m0 + wm2 + gr, mB = mA + 8;
        bool vA = mA < NTOK, vB = mB < NTOK;
        #pragma unroll
        for (int nt = 0; nt < 2; nt++) {
            float e0 = vA ? __expf(s[nt][0] * sc) : 0.f;
            float e1 = vA ? __expf(s[nt][1] * sc) : 0.f;
            float e2 = vB ? __expf(s[nt][2] * sc) : 0.f;
            float e3 = vB ? __expf(s[nt][3] * sc) : 0.f;
            colp[nt * 2]     += e0 + e2;
            colp[nt * 2 + 1] += e1 + e3;
            int col = wn2 + nt * 8 + 2 * gc;
            *(float2*)&sF[(wm2 + gr) * 72 + col]     = make_float2(e0, e1);
            *(float2*)&sF[(wm2 + gr + 8) * 72 + col] = make_float2(e2, e3);
        }
        __syncthreads();

        // Y GEMM: warp 64c x 32n, K=32
        #pragma unroll
        for (int kk = 0; kk < 32; kk += 8) {
            uint32_t a[4][4], bf[4][2];
            #pragma unroll
            for (int ct = 0; ct < 4; ct++) {
                int c0 = wc + ct * 16 + gr;
                a[ct][0] = fu(sG[c0 * 40 + kk + gc]);
                a[ct][1] = fu(sG[(c0 + 8) * 40 + kk + gc]);
                a[ct][2] = fu(sG[c0 * 40 + kk + gc + 4]);
                a[ct][3] = fu(sG[(c0 + 8) * 40 + kk + gc + 4]);
            }
            #pragma unroll
            for (int nt = 0; nt < 4; nt++) {
                bf[nt][0] = fu(sF[(kk + gc) * 72 + wn3 + nt * 8 + gr]);
                bf[nt][1] = fu(sF[(kk + gc + 4) * 72 + wn3 + nt * 8 + gr]);
            }
            #pragma unroll
            for (int ct = 0; ct < 4; ct++)
                #pragma unroll
                for (int nt = 0; nt < 4; nt++)
                    mma8(yacc[ct][nt], a[ct], bf[nt]);
        }
        __syncthreads();
    }

    // column sums -> sInv
    #pragma unroll
    for (int j = 0; j < 4; j++) {
        #pragma unroll
        for (int off = 4; off < 32; off <<= 1)
            colp[j] += __shfl_xor_sync(0xffffffffu, colp[j], off);
    }
    if (gr == 0) {
        #pragma unroll
        for (int nt = 0; nt < 2; nt++) {
            atomicAdd(&sSum[wn2 + nt * 8 + 2 * gc],     colp[nt * 2]);
            atomicAdd(&sSum[wn2 + nt * 8 + 2 * gc + 1], colp[nt * 2 + 1]);
        }
    }
    __syncthreads();
    if (tid < 64) sInv[tid] = 1.f / sSum[tid];
    __syncthreads();

    // scale + store Yw
    float* Yw = g_Yw + (size_t)w * C_ * MPAD;
    #pragma unroll
    for (int ct = 0; ct < 4; ct++) {
        int c0 = wc + ct * 16 + gr;
        size_t base0 = (size_t)c0 * MPAD;
        size_t base1 = base0 + 8 * MPAD;
        #pragma unroll
        for (int nt = 0; nt < 4; nt++) {
            int col = wn3 + nt * 8 + 2 * gc;
            int ng = nBase + col;
            if (ng < MPAD) {
                float i0 = sInv[col], i1 = sInv[col + 1];
                *(float2*)&Yw[base0 + ng] =
                    make_float2(yacc[ct][nt][0] * i0, yacc[ct][nt][1] * i1);
                *(float2*)&Yw[base1 + ng] =
                    make_float2(yacc[ct][nt][2] * i0, yacc[ct][nt][3] * i1);
            }
        }
    }
}

// ---------------------------------------------------------------------------
extern "C" void kernel_launch(void* const* d_in, const int* in_sizes, int n_in,
                              void* d_out, int out_size)
{
    const float* x       = (const float*)d_in[0];
    const float* w_theta = (const float*)d_in[1];
    const float* w_phi   = (const float*)d_in[2];
    const float* w_proj  = (const float*)d_in[3];
    float* out = (float*)d_out;

    void* pEw = nullptr;
    void* pYw = nullptr;
    cudaGetSymbolAddress(&pEw, g_Ew);
    cudaGetSymbolAddress(&pYw, g_Yw);

    cudaFuncSetAttribute(k_fattn, cudaFuncAttributeMaxDynamicSharedMemorySize, K2_SMEM);

    dim3 gp((HW_ + 127) / 128, 2, B_);   // (254, 2, 4)

    // 1) embeddings -> Ew windowed
    k_pw<0><<<gp, 256>>>(w_theta, w_phi, x, nullptr, (float*)pEw);
    // 2) fused scores + softmax + AV -> Yw windowed
    dim3 ga(6, NWIN);
    k_fattn<<<ga, 256, K2_SMEM>>>(x);
    // 3) out = x + w_proj @ Yw
    k_pw<1><<<gp, 256>>>(w_proj, w_proj + CE * C_, (const float*)pYw, x, out);
}

// round 5
// speedup vs baseline: 3.7845x; 1.1415x over previous
#include <cuda_runtime.h>
#include <cstdint>

#define B_    4
#define C_    256
#define CE    128
#define W_    180
#define WS_   18
#define HW_   32400
#define NTOK  324
#define NWIN  400
#define MPAD  336

// Scratch (device globals — no allocation allowed)
__device__ float g_Ew[(size_t)NWIN * C_ * MPAD];  // [w][chan][m] 0..127 theta, 128..255 phi
__device__ float g_Yf[(size_t)B_ * C_ * HW_];     // y flat (b,c,hw)

__device__ __forceinline__ void mma8(float* d, const uint32_t* a, const uint32_t* b) {
    asm volatile("mma.sync.aligned.m16n8k8.row.col.f32.tf32.tf32.f32 "
        "{%0,%1,%2,%3}, {%4,%5,%6,%7}, {%8,%9}, {%0,%1,%2,%3};"
        : "+f"(d[0]), "+f"(d[1]), "+f"(d[2]), "+f"(d[3])
        : "r"(a[0]), "r"(a[1]), "r"(a[2]), "r"(a[3]), "r"(b[0]), "r"(b[1]));
}
__device__ __forceinline__ uint32_t fu(float x) { return __float_as_uint(x); }
__device__ __forceinline__ void cp16(uint32_t dst, const void* src, bool v) {
    asm volatile("cp.async.cg.shared.global [%0], [%1], 16, %2;"
                 :: "r"(dst), "l"(src), "r"(v ? 16 : 0));
}
__device__ __forceinline__ void cp4(uint32_t dst, const void* src, bool v) {
    asm volatile("cp.async.ca.shared.global [%0], [%1], 4, %2;"
                 :: "r"(dst), "l"(src), "r"(v ? 4 : 0));
}
#define CP_COMMIT() asm volatile("cp.async.commit_group;")

// ---------------------------------------------------------------------------
// k_pw<MODE>: Out[e][p] = sum_c A[e][c] * B[c][p], B flat (b,c,hw).
// MODE 0: out -> Ew windowed (no resid). MODE 1: out flat + resid.
// BM=128 BN=128 BK=16, cp.async 2-stage double buffer.
// ---------------------------------------------------------------------------
template<int MODE>
__global__ __launch_bounds__(256, 2) void k_pw(
    const float* __restrict__ Alo, const float* __restrict__ Ahi,
    const float* __restrict__ Bsrc, const float* __restrict__ resid,
    float* __restrict__ Out)
{
    __shared__ float As[2][128][20];
    __shared__ float Bs[2][16][136];
    const int b = blockIdx.z, eBase = blockIdx.y * 128, pBase = blockIdx.x * 128;
    const int tid = threadIdx.x, lane = tid & 31, wid = tid >> 5;
    const int wm = (wid >> 2) * 64, wn = (wid & 3) * 32;
    const int gr = lane >> 2, gc = lane & 3;
    const float* Asrc = (eBase == 0) ? Alo : Ahi;      // tile-aligned weight halves
    const float* Bb = Bsrc + (size_t)b * C_ * HW_;
    const uint32_t asB = (uint32_t)__cvta_generic_to_shared(&As[0][0][0]);
    const uint32_t bsB = (uint32_t)__cvta_generic_to_shared(&Bs[0][0][0]);

    auto issue = [&](int s, int k0) {
        #pragma unroll
        for (int l = 0; l < 2; l++) {
            int c = tid + l * 256;
            int row = c >> 2, kc = (c & 3) * 4;
            cp16(asB + (uint32_t)(s * 2560 + row * 20 + kc) * 4,
                 Asrc + row * 256 + k0 + kc, true);
        }
        #pragma unroll
        for (int l = 0; l < 2; l++) {
            int c = tid + l * 256;
            int k = c >> 5, pc = (c & 31) * 4;
            cp16(bsB + (uint32_t)(s * 2176 + k * 136 + pc) * 4,
                 Bb + (size_t)(k0 + k) * HW_ + pBase + pc, pBase + pc < HW_);
        }
        CP_COMMIT();
    };

    float acc[4][4][4] = {};

    issue(0, 0);
    for (int it = 0; it < 16; it++) {
        if (it < 15) {
            issue((it + 1) & 1, (it + 1) * 16);
            asm volatile("cp.async.wait_group 1;");
        } else {
            asm volatile("cp.async.wait_group 0;");
        }
        __syncthreads();
        const int s = it & 1;
        #pragma unroll
        for (int kk = 0; kk < 16; kk += 8) {
            uint32_t a[4][4], bf[4][2];
            #pragma unroll
            for (int mt = 0; mt < 4; mt++) {
                int r0 = wm + mt * 16 + gr;
                a[mt][0] = fu(As[s][r0][kk + gc]);
                a[mt][1] = fu(As[s][r0 + 8][kk + gc]);
                a[mt][2] = fu(As[s][r0][kk + gc + 4]);
                a[mt][3] = fu(As[s][r0 + 8][kk + gc + 4]);
            }
            #pragma unroll
            for (int nt = 0; nt < 4; nt++) {
                bf[nt][0] = fu(Bs[s][kk + gc][wn + nt * 8 + gr]);
                bf[nt][1] = fu(Bs[s][kk + gc + 4][wn + nt * 8 + gr]);
            }
            #pragma unroll
            for (int mt = 0; mt < 4; mt++)
                #pragma unroll
                for (int nt = 0; nt < 4; nt++)
                    mma8(acc[mt][nt], a[mt], bf[nt]);
        }
        __syncthreads();
    }

    #pragma unroll
    for (int nt = 0; nt < 4; nt++) {
        int p = pBase + wn + nt * 8 + 2 * gc;
        if (p >= HW_) continue;
        if (MODE == 0) {
            int gh = p / W_, gw = p - gh * W_;
            int w = b * 100 + (gh / WS_) * 10 + gw / WS_;
            int m = (gh % WS_) * WS_ + gw % WS_;
            size_t rowOff = (size_t)w * (C_ * MPAD) + m;
            #pragma unroll
            for (int mt = 0; mt < 4; mt++)
                #pragma unroll
                for (int half = 0; half < 2; half++) {
                    int e = eBase + wm + mt * 16 + gr + half * 8;
                    *(float2*)&Out[rowOff + (size_t)e * MPAD] =
                        make_float2(acc[mt][nt][half * 2], acc[mt][nt][half * 2 + 1]);
                }
        } else {
            #pragma unroll
            for (int mt = 0; mt < 4; mt++)
                #pragma unroll
                for (int half = 0; half < 2; half++) {
                    int e = eBase + wm + mt * 16 + gr + half * 8;
                    size_t rowb = ((size_t)b * C_ + e) * HW_;
                    float2 r = *(const float2*)&resid[rowb + p];
                    *(float2*)&Out[rowb + p] =
                        make_float2(acc[mt][nt][half * 2] + r.x,
                                    acc[mt][nt][half * 2 + 1] + r.y);
                }
        }
    }
}

// ---------------------------------------------------------------------------
// Fused attention: CTA = (window, 128-query tile), 512 threads, cp.async
// double-buffered phi/G over 32-key m-tiles. Y written flat (b,c,hw).
// smem ~206KB -> 1 CTA/SM.
// ---------------------------------------------------------------------------
#define FA_TH_OFF   0                      // [128][136]
#define FA_PHI_OFF  17408                  // [2][128][40]
#define FA_G_OFF    27648                  // [2][256][40]
#define FA_F_OFF    48128                  // [32][136]
#define FA_SUM_OFF  52480                  // [128]
#define FA_INV_OFF  52608                  // [128]
#define FA_SMEM_FLT 52736
#define FA_SMEM_B   (FA_SMEM_FLT * 4)

__global__ __launch_bounds__(512, 1) void k_fattn(const float* __restrict__ x)
{
    extern __shared__ float sm[];
    float* sTh  = sm + FA_TH_OFF;
    float* sPhi = sm + FA_PHI_OFF;
    float* sG   = sm + FA_G_OFF;
    float* sF   = sm + FA_F_OFF;
    float* sSum = sm + FA_SUM_OFF;
    float* sInv = sm + FA_INV_OFF;

    const int w = blockIdx.y, nBase = blockIdx.x * 128;
    const int b = w / 100, ih = (w / 10) % 10, iw = w % 10;
    const int tid = threadIdx.x, lane = tid & 31, wid = tid >> 5;
    const int gr = lane >> 2, gc = lane & 3;
    const int swm = (wid >> 3) * 16, swn = (wid & 7) * 16;   // S: 2(m)x8(n)
    const int ywc = (wid >> 2) * 64, ywn = (wid & 3) * 32;   // Y: 4(c)x4(n)
    const float* Ew = g_Ew + (size_t)w * C_ * MPAD;
    const float* xb = x + (size_t)b * C_ * HW_;
    const int hwBase = (ih * WS_) * W_ + iw * WS_;
    const float sc = 0.08838834764831843f;  // 1/sqrt(128)
    const uint32_t phiB = (uint32_t)__cvta_generic_to_shared(sPhi);
    const uint32_t gB   = (uint32_t)__cvta_generic_to_shared(sG);

    // theta (once): sTh[e][n], zero-padded n
    for (int c = tid; c < 4096; c += 512) {
        int e = c >> 5, nc = (c & 31) * 4;
        int ng = nBase + nc;
        float4 v = make_float4(0.f, 0.f, 0.f, 0.f);
        if (ng < NTOK) v = *(const float4*)(Ew + (size_t)e * MPAD + ng);
        *(float4*)(sTh + e * 136 + nc) = v;
    }
    if (tid < 128) sSum[tid] = 0.f;

    // per-thread invariant gather coords for G
    const int mrel = tid & 31;
    const int phiMc = (tid & 7) * 4;

    auto issue = [&](int s, int m0) {
        bool pv = (m0 + phiMc) < NTOK;   // NTOK multiple of 4 -> chunk all-or-none
        #pragma unroll
        for (int l = 0; l < 2; l++) {
            int e = (tid >> 3) + l * 64;
            cp16(phiB + (uint32_t)((s * 128 + e) * 40 + phiMc) * 4,
                 Ew + (size_t)(CE + e) * MPAD + m0 + phiMc, pv);
        }
        int mg = m0 + mrel;
        bool gv = mg < NTOK;
        int mm = gv ? mg : 0;
        const float* gsrc = xb + hwBase + (mm / WS_) * W_ + mm % WS_;
        #pragma unroll
        for (int l = 0; l < 16; l++) {
            int cc = (tid >> 5) + l * 16;
            cp4(gB + (uint32_t)((s * 256 + cc) * 40 + mrel) * 4,
                gsrc + (size_t)cc * HW_, gv);
        }
        CP_COMMIT();
    };

    float yacc[4][4][4] = {};
    float colp[4] = {};

    issue(0, 0);
    __syncthreads();   // covers sTh + sSum init

    for (int mi = 0; mi < 11; mi++) {
        int m0 = mi * 32;
        if (mi < 10) {
            issue((mi + 1) & 1, (mi + 1) * 32);
            asm volatile("cp.async.wait_group 1;");
        } else {
            asm volatile("cp.async.wait_group 0;");
        }
        __syncthreads();
        const int st = mi & 1;
        const float* phiS = sPhi + st * (128 * 40);
        const float* gS   = sG + st * (256 * 40);

        // S: warp 16m x 16n, K=128
        float sacc[2][4] = {};
        #pragma unroll
        for (int kk = 0; kk < 128; kk += 8) {
            uint32_t a[4];
            a[0] = fu(phiS[(kk + gc) * 40 + swm + gr]);
            a[1] = fu(phiS[(kk + gc) * 40 + swm + gr + 8]);
            a[2] = fu(phiS[(kk + gc + 4) * 40 + swm + gr]);
            a[3] = fu(phiS[(kk + gc + 4) * 40 + swm + gr + 8]);
            #pragma unroll
            for (int nt = 0; nt < 2; nt++) {
                uint32_t bb[2];
                bb[0] = fu(sTh[(kk + gc) * 136 + swn + nt * 8 + gr]);
                bb[1] = fu(sTh[(kk + gc + 4) * 136 + swn + nt * 8 + gr]);
                mma8(sacc[nt], a, bb);
            }
        }

        // exp + mask + sF + colsum partials
        int mA = m0 + swm + gr;
        bool vA = mA < NTOK, vB = (mA + 8) < NTOK;
        #pragma unroll
        for (int nt = 0; nt < 2; nt++) {
            float e0 = vA ? __expf(sacc[nt][0] * sc) : 0.f;
            float e1 = vA ? __expf(sacc[nt][1] * sc) : 0.f;
            float e2 = vB ? __expf(sacc[nt][2] * sc) : 0.f;
            float e3 = vB ? __expf(sacc[nt][3] * sc) : 0.f;
            colp[nt * 2]     += e0 + e2;
            colp[nt * 2 + 1] += e1 + e3;
            int col = swn + nt * 8 + 2 * gc;
            *(float2*)&sF[(swm + gr) * 136 + col]     = make_float2(e0, e1);
            *(float2*)&sF[(swm + gr + 8) * 136 + col] = make_float2(e2, e3);
        }
        __syncthreads();

        // Y: warp 64c x 32n, K=32
        #pragma unroll
        for (int kk = 0; kk < 32; kk += 8) {
            uint32_t a[4][4], bf[4][2];
            #pragma unroll
            for (int ct = 0; ct < 4; ct++) {
                int c0 = ywc + ct * 16 + gr;
                a[ct][0] = fu(gS[c0 * 40 + kk + gc]);
                a[ct][1] = fu(gS[(c0 + 8) * 40 + kk + gc]);
                a[ct][2] = fu(gS[c0 * 40 + kk + gc + 4]);
                a[ct][3] = fu(gS[(c0 + 8) * 40 + kk + gc + 4]);
            }
            #pragma unroll
            for (int nt = 0; nt < 4; nt++) {
                bf[nt][0] = fu(sF[(kk + gc) * 136 + ywn + nt * 8 + gr]);
                bf[nt][1] = fu(sF[(kk + gc + 4) * 136 + ywn + nt * 8 + gr]);
            }
            #pragma unroll
            for (int ct = 0; ct < 4; ct++)
                #pragma unroll
                for (int nt = 0; nt < 4; nt++)
                    mma8(yacc[ct][nt], a[ct], bf[nt]);
        }
        __syncthreads();
    }

    // column sums -> sInv
    #pragma unroll
    for (int j = 0; j < 4; j++) {
        #pragma unroll
        for (int off = 4; off < 32; off <<= 1)
            colp[j] += __shfl_xor_sync(0xffffffffu, colp[j], off);
    }
    if (gr == 0) {
        #pragma unroll
        for (int nt = 0; nt < 2; nt++) {
            atomicAdd(&sSum[swn + nt * 8 + 2 * gc],     colp[nt * 2]);
            atomicAdd(&sSum[swn + nt * 8 + 2 * gc + 1], colp[nt * 2 + 1]);
        }
    }
    __syncthreads();
    if (tid < 128) sInv[tid] = 1.f / sSum[tid];
    __syncthreads();

    // scale + store flat (pairs stay within window rows: col even, WS even)
    float* Yb = g_Yf + (size_t)b * C_ * HW_;
    #pragma unroll
    for (int ct = 0; ct < 4; ct++) {
        int c0 = ywc + ct * 16 + gr;
        #pragma unroll
        for (int nt = 0; nt < 4; nt++) {
            int col = ywn + nt * 8 + 2 * gc;
            int ng = nBase + col;
            if (ng < NTOK) {
                int hw0 = hwBase + (ng / WS_) * W_ + ng % WS_;
                float i0 = sInv[col], i1 = sInv[col + 1];
                *(float2*)&Yb[(size_t)c0 * HW_ + hw0] =
                    make_float2(yacc[ct][nt][0] * i0, yacc[ct][nt][1] * i1);
                *(float2*)&Yb[(size_t)(c0 + 8) * HW_ + hw0] =
                    make_float2(yacc[ct][nt][2] * i0, yacc[ct][nt][3] * i1);
            }
        }
    }
}

// ---------------------------------------------------------------------------
extern "C" void kernel_launch(void* const* d_in, const int* in_sizes, int n_in,
                              void* d_out, int out_size)
{
    const float* x       = (const float*)d_in[0];
    const float* w_theta = (const float*)d_in[1];
    const float* w_phi   = (const float*)d_in[2];
    const float* w_proj  = (const float*)d_in[3];
    float* out = (float*)d_out;

    void* pEw = nullptr;
    void* pYf = nullptr;
    cudaGetSymbolAddress(&pEw, g_Ew);
    cudaGetSymbolAddress(&pYf, g_Yf);

    cudaFuncSetAttribute(k_fattn, cudaFuncAttributeMaxDynamicSharedMemorySize, FA_SMEM_B);

    dim3 gp((HW_ + 127) / 128, 2, B_);   // (254, 2, 4)

    // 1) embeddings -> Ew windowed
    k_pw<0><<<gp, 256>>>(w_theta, w_phi, x, nullptr, (float*)pEw);
    // 2) fused scores + softmax + AV -> Yf flat
    dim3 ga(3, NWIN);
    k_fattn<<<ga, 512, FA_SMEM_B>>>(x);
    // 3) out = x + w_proj @ Yf
    k_pw<1><<<gp, 256>>>(w_proj, w_proj + CE * C_, (const float*)pYf, x, out);
}

// round 6
// speedup vs baseline: 4.9706x; 1.3134x over previous
#include <cuda_runtime.h>
#include <cuda_fp16.h>
#include <cstdint>

#define B_    4
#define C_    256
#define CE    128
#define W_    180
#define WS_   18
#define HW_   32400
#define NTOK  324
#define NWIN  400
#define MP2   384          // padded tokens per window

// Scratch (device globals — no allocation allowed)
__device__ __half g_Xw[(size_t)NWIN * MP2 * C_];   // [w][m][c]   (c contiguous)
__device__ __half g_Xc[(size_t)NWIN * C_ * MP2];   // [w][c][m]   (m contiguous)
__device__ __half g_Ewh[(size_t)NWIN * MP2 * C_];  // [w][m][chan] 0..127 theta, 128..255 phi
__device__ __half g_Yh[(size_t)B_ * HW_ * C_];     // [b][hw][c]
__device__ __half g_wh[512 * 256];                 // rows 0..255 [w_theta;w_phi], 256..511 w_proj

__device__ __forceinline__ void mma16(float* d, const uint32_t* a, const uint32_t* b) {
    asm volatile("mma.sync.aligned.m16n8k16.row.col.f32.f16.f16.f32 "
        "{%0,%1,%2,%3}, {%4,%5,%6,%7}, {%8,%9}, {%0,%1,%2,%3};"
        : "+f"(d[0]), "+f"(d[1]), "+f"(d[2]), "+f"(d[3])
        : "r"(a[0]), "r"(a[1]), "r"(a[2]), "r"(a[3]), "r"(b[0]), "r"(b[1]));
}
__device__ __forceinline__ uint32_t lh2(const __half* p) { return *(const uint32_t*)p; }
__device__ __forceinline__ uint32_t pack2(float a, float b) {
    __half2 h = __floats2half2_rn(a, b);
    return *(uint32_t*)&h;
}
__device__ __forceinline__ void cp16h(uint32_t dst, const __half* src) {
    asm volatile("cp.async.cg.shared.global [%0], [%1], 16;" :: "r"(dst), "l"(src));
}
__device__ __forceinline__ void cp16p(uint32_t dst, const __half* src, bool v) {
    asm volatile("cp.async.cg.shared.global [%0], [%1], 16, %2;"
                 :: "r"(dst), "l"(src), "r"(v ? 16 : 0));
}
#define CP_COMMIT() asm volatile("cp.async.commit_group;")

// ---------------------------------------------------------------------------
// Prep: x -> Xw[w][m][c] and Xc[w][c][m] (half, zero-padded m>=324); weights -> wh.
// ---------------------------------------------------------------------------
__global__ __launch_bounds__(256) void k_prep(
    const float* __restrict__ x, const float* __restrict__ wt,
    const float* __restrict__ wp, const float* __restrict__ wj)
{
    __shared__ __half sT[64][384];
    const int blk = blockIdx.x, tid = threadIdx.x;
    if (blk >= NWIN) {
        int wb = blk - NWIN;
        for (int idx = tid; idx < 32768; idx += 256) {
            int row = wb * 128 + (idx >> 8), c = idx & 255;
            float v;
            if (row < 128)      v = wt[row * 256 + c];
            else if (row < 256) v = wp[(row - 128) * 256 + c];
            else                v = wj[(row - 256) * 256 + c];
            g_wh[row * 256 + c] = __float2half(v);
        }
        return;
    }
    const int w = blk, b = w / 100, ih = (w / 10) % 10, iw = w % 10;
    const int hwBase = ih * WS_ * W_ + iw * WS_;
    const int lane = tid & 31, wid = tid >> 5;
    __half* Xw = g_Xw + (size_t)w * MP2 * C_;
    __half* Xc = g_Xc + (size_t)w * C_ * MP2;

    for (int c0 = 0; c0 < C_; c0 += 64) {
        for (int l = 0; l < 8; l++) {
            int ci = wid + l * 8;
            const float* xs = x + (size_t)(b * C_ + c0 + ci) * HW_ + hwBase;
            for (int m = lane; m < MP2; m += 32) {
                float v = 0.f;
                if (m < NTOK) v = xs[(m / WS_) * W_ + m % WS_];
                sT[ci][m] = __float2half(v);
            }
        }
        __syncthreads();
        {   // Xw[m][c] : half2 along c
            int cj = (lane) * 2;
            for (int m = (tid >> 5); m < MP2; m += 8) {
                uint32_t v = ((uint32_t)__half_as_ushort(sT[cj + 1][m]) << 16)
                           | (uint32_t)__half_as_ushort(sT[cj][m]);
                *(uint32_t*)&Xw[(size_t)m * C_ + c0 + cj] = v;
            }
        }
        for (int l = 0; l < 8; l++) {   // Xc[c][m] : u64 along m
            int ci = (tid >> 5) + l * 8;
            for (int mm = lane * 4; mm < MP2; mm += 128)
                *(uint64_t*)&Xc[(size_t)(c0 + ci) * MP2 + mm] =
                    *(const uint64_t*)&sT[ci][mm];
        }
        __syncthreads();
    }
}

// ---------------------------------------------------------------------------
// pw0: E'[m][e] = Xw[m][c] @ wh[e][c]^T per window. BM=64 m, BN=256 e, K=256.
// 8 warps = 4(m) x 2(e): warp 16m x 128e. Double-buffered cp.async, BK=32.
// ---------------------------------------------------------------------------
#define PW0_SMEM ((2 * 64 * 40 + 2 * 256 * 40) * 2)

__global__ __launch_bounds__(256, 2) void k_pw0()
{
    extern __shared__ __half ps[];
    __half* sA = ps;                  // [2][64][40]
    __half* sB = ps + 2 * 64 * 40;    // [2][256][40]
    const int w = blockIdx.y, mBase = blockIdx.x * 64;
    const int tid = threadIdx.x, lane = tid & 31, wid = tid >> 5;
    const int wm = (wid >> 1) * 16, we = (wid & 1) * 128;
    const int gr = lane >> 2, gc = lane & 3;
    const __half* Xw = g_Xw + (size_t)w * MP2 * C_ + (size_t)mBase * C_;
    const uint32_t aB = (uint32_t)__cvta_generic_to_shared(sA);
    const uint32_t bB = (uint32_t)__cvta_generic_to_shared(sB);

    auto issue = [&](int s, int k0) {
        {
            int r = tid >> 2, ch = (tid & 3) * 8;
            cp16h(aB + (uint32_t)(s * 2560 + r * 40 + ch) * 2,
                  Xw + (size_t)r * C_ + k0 + ch);
        }
        #pragma unroll
        for (int l = 0; l < 4; l++) {
            int idx = tid + l * 256;
            int e = idx >> 2, ch = (idx & 3) * 8;
            cp16h(bB + (uint32_t)(s * 10240 + e * 40 + ch) * 2,
                  g_wh + e * 256 + k0 + ch);
        }
        CP_COMMIT();
    };

    float acc[16][4] = {};
    issue(0, 0);
    for (int it = 0; it < 8; it++) {
        if (it < 7) { issue((it + 1) & 1, (it + 1) * 32);
                      asm volatile("cp.async.wait_group 1;"); }
        else        { asm volatile("cp.async.wait_group 0;"); }
        __syncthreads();
        const __half* As = sA + (it & 1) * 2560;
        const __half* Bs = sB + (it & 1) * 10240;
        #pragma unroll
        for (int ks = 0; ks < 2; ks++) {
            int kk = ks * 16;
            uint32_t a[4];
            a[0] = lh2(As + (wm + gr) * 40 + kk + 2 * gc);
            a[1] = lh2(As + (wm + gr + 8) * 40 + kk + 2 * gc);
            a[2] = lh2(As + (wm + gr) * 40 + kk + 2 * gc + 8);
            a[3] = lh2(As + (wm + gr + 8) * 40 + kk + 2 * gc + 8);
            #pragma unroll
            for (int et = 0; et < 16; et++) {
                uint32_t bb[2];
                bb[0] = lh2(Bs + (we + et * 8 + gr) * 40 + kk + 2 * gc);
                bb[1] = lh2(Bs + (we + et * 8 + gr) * 40 + kk + 2 * gc + 8);
                mma16(acc[et], a, bb);
            }
        }
        __syncthreads();
    }

    __half* Eo = g_Ewh + (size_t)w * MP2 * C_;
    int m0r = mBase + wm + gr;
    #pragma unroll
    for (int et = 0; et < 16; et++) {
        int e = we + et * 8 + 2 * gc;
        *(uint32_t*)&Eo[(size_t)m0r * C_ + e]       = pack2(acc[et][0], acc[et][1]);
        *(uint32_t*)&Eo[(size_t)(m0r + 8) * C_ + e] = pack2(acc[et][2], acc[et][3]);
    }
}

// ---------------------------------------------------------------------------
// Fused attention (fp16): CTA = (window, 64-query tile), 256 thr, 2 CTAs/SM.
// S'[n][m] = theta[n][e] x phi[m][e]; F' = exp(S'*sc); Y'[n][c] = F'[n][m] x G[c][m].
// ---------------------------------------------------------------------------
#define FA_SMEM_B (17408 + 17408 + 40960 + 5120 + 512)

__global__ __launch_bounds__(256, 2) void k_fattn()
{
    extern __shared__ __half fs[];
    __half* sTh  = fs;                    // [64][136]
    __half* sPhi = sTh + 64 * 136;        // [2][32][136]
    __half* sG   = sPhi + 2 * 32 * 136;   // [2][256][40]
    __half* sF   = sG + 2 * 256 * 40;     // [64][40]
    float*  sSum = (float*)(sF + 64 * 40);  // [64]
    float*  sInv = sSum + 64;               // [64]

    const int w = blockIdx.y, nBase = blockIdx.x * 64;
    const int b = w / 100, ih = (w / 10) % 10, iw = w % 10;
    const int tid = threadIdx.x, lane = tid & 31, wid = tid >> 5;
    const int gr = lane >> 2, gc = lane & 3;
    const int wn = (wid >> 1) * 16;     // n-range, both phases
    const int wmS = (wid & 1) * 16;     // S-phase m
    const int wcY = (wid & 1) * 128;    // Y-phase c
    const __half* Eww = g_Ewh + (size_t)w * MP2 * C_;
    const __half* Xc  = g_Xc + (size_t)w * C_ * MP2;
    const float SC = 0.08838834764831843f;  // 1/sqrt(128)
    const uint32_t thB = (uint32_t)__cvta_generic_to_shared(sTh);
    const uint32_t phB = (uint32_t)__cvta_generic_to_shared(sPhi);
    const uint32_t gBB = (uint32_t)__cvta_generic_to_shared(sG);

    if (tid < 64) sSum[tid] = 0.f;

    // theta once: sTh[n][e]
    #pragma unroll
    for (int l = 0; l < 4; l++) {
        int idx = tid + l * 256;
        int n = idx >> 4, ch = (idx & 15) * 8;
        cp16h(thB + (uint32_t)(n * 136 + ch) * 2, Eww + (size_t)(nBase + n) * C_ + ch);
    }

    auto issue = [&](int s, int m0) {
        #pragma unroll
        for (int l = 0; l < 2; l++) {
            int idx = tid + l * 256;
            int m = idx >> 4, ch = (idx & 15) * 8;
            cp16h(phB + (uint32_t)((s * 32 + m) * 136 + ch) * 2,
                  Eww + (size_t)(m0 + m) * C_ + CE + ch);
        }
        #pragma unroll
        for (int l = 0; l < 4; l++) {
            int idx = tid + l * 256;
            int c = idx >> 2, ch = (idx & 3) * 8;
            cp16h(gBB + (uint32_t)((s * 256 + c) * 40 + ch) * 2,
                  Xc + (size_t)c * MP2 + m0 + ch);
        }
        CP_COMMIT();
    };

    float yacc[16][4] = {};
    float colp[2] = {};

    issue(0, 0);     // commits theta + buffer 0
    for (int mi = 0; mi < 11; mi++) {
        int m0 = mi * 32;
        if (mi < 10) { issue((mi + 1) & 1, m0 + 32);
                       asm volatile("cp.async.wait_group 1;"); }
        else         { asm volatile("cp.async.wait_group 0;"); }
        __syncthreads();
        const __half* ph = sPhi + (mi & 1) * 32 * 136;
        const __half* gS = sG + (mi & 1) * 256 * 40;

        // S'
        float sacc[2][4] = {};
        #pragma unroll
        for (int ks = 0; ks < 8; ks++) {
            int kk = ks * 16;
            uint32_t a[4];
            a[0] = lh2(sTh + (wn + gr) * 136 + kk + 2 * gc);
            a[1] = lh2(sTh + (wn + gr + 8) * 136 + kk + 2 * gc);
            a[2] = lh2(sTh + (wn + gr) * 136 + kk + 2 * gc + 8);
            a[3] = lh2(sTh + (wn + gr + 8) * 136 + kk + 2 * gc + 8);
            #pragma unroll
            for (int t = 0; t < 2; t++) {
                uint32_t bb[2];
                bb[0] = lh2(ph + (wmS + t * 8 + gr) * 136 + kk + 2 * gc);
                bb[1] = lh2(ph + (wmS + t * 8 + gr) * 136 + kk + 2 * gc + 8);
                mma16(sacc[t], a, bb);
            }
        }
        // exp + mask + sF[n][m] + colsum partials
        #pragma unroll
        for (int t = 0; t < 2; t++) {
            int mg = m0 + wmS + t * 8 + 2 * gc;
            bool v = mg < NTOK;
            float e0 = v ? __expf(sacc[t][0] * SC) : 0.f;
            float e1 = v ? __expf(sacc[t][1] * SC) : 0.f;
            float e2 = v ? __expf(sacc[t][2] * SC) : 0.f;
            float e3 = v ? __expf(sacc[t][3] * SC) : 0.f;
            colp[0] += e0 + e1;
            colp[1] += e2 + e3;
            *(uint32_t*)&sF[(wn + gr) * 40 + wmS + t * 8 + 2 * gc]     = pack2(e0, e1);
            *(uint32_t*)&sF[(wn + gr + 8) * 40 + wmS + t * 8 + 2 * gc] = pack2(e2, e3);
        }
        __syncthreads();

        // Y'
        #pragma unroll
        for (int ks = 0; ks < 2; ks++) {
            int kk = ks * 16;
            uint32_t a[4];
            a[0] = lh2(sF + (wn + gr) * 40 + kk + 2 * gc);
            a[1] = lh2(sF + (wn + gr + 8) * 40 + kk + 2 * gc);
            a[2] = lh2(sF + (wn + gr) * 40 + kk + 2 * gc + 8);
            a[3] = lh2(sF + (wn + gr + 8) * 40 + kk + 2 * gc + 8);
            #pragma unroll
            for (int ct = 0; ct < 16; ct++) {
                uint32_t bb[2];
                bb[0] = lh2(gS + (wcY + ct * 8 + gr) * 40 + kk + 2 * gc);
                bb[1] = lh2(gS + (wcY + ct * 8 + gr) * 40 + kk + 2 * gc + 8);
                mma16(yacc[ct], a, bb);
            }
        }
        __syncthreads();
    }

    // column sums (over m) per n
    colp[0] += __shfl_xor_sync(0xffffffffu, colp[0], 1);
    colp[0] += __shfl_xor_sync(0xffffffffu, colp[0], 2);
    colp[1] += __shfl_xor_sync(0xffffffffu, colp[1], 1);
    colp[1] += __shfl_xor_sync(0xffffffffu, colp[1], 2);
    if (gc == 0) {
        atomicAdd(&sSum[wn + gr], colp[0]);
        atomicAdd(&sSum[wn + gr + 8], colp[1]);
    }
    __syncthreads();
    if (tid < 64) sInv[tid] = 1.f / sSum[tid];
    __syncthreads();

    // scale + store Yh[b][hw][c] (half2 along c)
    const int hwBase = ih * WS_ * W_ + iw * WS_;
    __half* Yb = g_Yh + (size_t)b * HW_ * C_;
    int n0 = nBase + wn + gr, n1 = n0 + 8;
    bool v0 = n0 < NTOK, v1 = n1 < NTOK;
    float i0 = sInv[wn + gr], i1 = sInv[wn + gr + 8];
    size_t r0 = v0 ? (size_t)(hwBase + (n0 / WS_) * W_ + n0 % WS_) * C_ : 0;
    size_t r1 = v1 ? (size_t)(hwBase + (n1 / WS_) * W_ + n1 % WS_) * C_ : 0;
    #pragma unroll
    for (int ct = 0; ct < 16; ct++) {
        int c = wcY + ct * 8 + 2 * gc;
        if (v0) *(uint32_t*)&Yb[r0 + c] = pack2(yacc[ct][0] * i0, yacc[ct][1] * i0);
        if (v1) *(uint32_t*)&Yb[r1 + c] = pack2(yacc[ct][2] * i1, yacc[ct][3] * i1);
    }
}

// ---------------------------------------------------------------------------
// pw1: out[o][p] = x + wproj[o][c] @ Yh[p][c]^T. BM=128 o, BN=128 p, K=256.
// 8 warps = 2(o) x 4(p): warp 64o x 32p.
// ---------------------------------------------------------------------------
__global__ __launch_bounds__(256, 2) void k_pw1(
    const float* __restrict__ x, float* __restrict__ out)
{
    __shared__ __half sA[2][128][40];
    __shared__ __half sB[2][128][40];
    const int b = blockIdx.z, oBase = blockIdx.y * 128, pBase = blockIdx.x * 128;
    const int tid = threadIdx.x, lane = tid & 31, wid = tid >> 5;
    const int wo = (wid >> 2) * 64, wp = (wid & 3) * 32;
    const int gr = lane >> 2, gc = lane & 3;
    const __half* Yb = g_Yh + (size_t)b * HW_ * C_;
    const uint32_t aB = (uint32_t)__cvta_generic_to_shared(&sA[0][0][0]);
    const uint32_t bB = (uint32_t)__cvta_generic_to_shared(&sB[0][0][0]);

    auto issue = [&](int s, int k0) {
        #pragma unroll
        for (int l = 0; l < 2; l++) {
            int idx = tid + l * 256;
            int r = idx >> 2, ch = (idx & 3) * 8;
            cp16h(aB + (uint32_t)(s * 5120 + r * 40 + ch) * 2,
                  g_wh + (256 + oBase + r) * 256 + k0 + ch);
        }
        #pragma unroll
        for (int l = 0; l < 2; l++) {
            int idx = tid + l * 256;
            int p = idx >> 2, ch = (idx & 3) * 8;
            int pg = pBase + p;
            bool v = pg < HW_;
            cp16p(bB + (uint32_t)(s * 5120 + p * 40 + ch) * 2,
                  Yb + (size_t)(v ? pg : 0) * C_ + k0 + ch, v);
        }
        CP_COMMIT();
    };

    float acc[4][4][4] = {};
    issue(0, 0);
    for (int it = 0; it < 8; it++) {
        if (it < 7) { issue((it + 1) & 1, (it + 1) * 32);
                      asm volatile("cp.async.wait_group 1;"); }
        else        { asm volatile("cp.async.wait_group 0;"); }
        __syncthreads();
        const __half* As = &sA[it & 1][0][0];
        const __half* Bs = &sB[it & 1][0][0];
        #pragma unroll
        for (int ks = 0; ks < 2; ks++) {
            int kk = ks * 16;
            uint32_t a[4][4], bb[4][2];
            #pragma unroll
            for (int ot = 0; ot < 4; ot++) {
                int r0 = wo + ot * 16 + gr;
                a[ot][0] = lh2(As + r0 * 40 + kk + 2 * gc);
                a[ot][1] = lh2(As + (r0 + 8) * 40 + kk + 2 * gc);
                a[ot][2] = lh2(As + r0 * 40 + kk + 2 * gc + 8);
                a[ot][3] = lh2(As + (r0 + 8) * 40 + kk + 2 * gc + 8);
            }
            #pragma unroll
            for (int pt = 0; pt < 4; pt++) {
                bb[pt][0] = lh2(Bs + (wp + pt * 8 + gr) * 40 + kk + 2 * gc);
                bb[pt][1] = lh2(Bs + (wp + pt * 8 + gr) * 40 + kk + 2 * gc + 8);
            }
            #pragma unroll
            for (int ot = 0; ot < 4; ot++)
                #pragma unroll
                for (int pt = 0; pt < 4; pt++)
                    mma16(acc[ot][pt], a[ot], bb[pt]);
        }
        __syncthreads();
    }

    #pragma unroll
    for (int ot = 0; ot < 4; ot++) {
        int o0 = oBase + wo + ot * 16 + gr;
        size_t row0 = ((size_t)b * C_ + o0) * HW_;
        size_t row1 = ((size_t)b * C_ + o0 + 8) * HW_;
        #pragma unroll
        for (int pt = 0; pt < 4; pt++) {
            int p = pBase + wp + pt * 8 + 2 * gc;
            if (p < HW_) {
                float2 r0 = *(const float2*)&x[row0 + p];
                float2 r1 = *(const float2*)&x[row1 + p];
                *(float2*)&out[row0 + p] =
                    make_float2(acc[ot][pt][0] + r0.x, acc[ot][pt][1] + r0.y);
                *(float2*)&out[row1 + p] =
                    make_float2(acc[ot][pt][2] + r1.x, acc[ot][pt][3] + r1.y);
            }
        }
    }
}

// ---------------------------------------------------------------------------
extern "C" void kernel_launch(void* const* d_in, const int* in_sizes, int n_in,
                              void* d_out, int out_size)
{
    const float* x       = (const float*)d_in[0];
    const float* w_theta = (const float*)d_in[1];
    const float* w_phi   = (const float*)d_in[2];
    const float* w_proj  = (const float*)d_in[3];
    float* out = (float*)d_out;

    cudaFuncSetAttribute(k_pw0, cudaFuncAttributeMaxDynamicSharedMemorySize, PW0_SMEM);
    cudaFuncSetAttribute(k_fattn, cudaFuncAttributeMaxDynamicSharedMemorySize, FA_SMEM_B);

    // 1) convert x (two layouts) + weights to half
    k_prep<<<NWIN + 4, 256>>>(x, w_theta, w_phi, w_proj);
    // 2) embeddings -> Ewh[w][m][chan]
    dim3 g0(6, NWIN);
    k_pw0<<<g0, 256, PW0_SMEM>>>();
    // 3) fused attention -> Yh[b][hw][c]
    dim3 gf(6, NWIN);
    k_fattn<<<gf, 256, FA_SMEM_B>>>();
    // 4) out = x + w_proj @ Y
    dim3 g1(254, 2, B_);
    k_pw1<<<g1, 256>>>(x, out);
}

// round 7
// speedup vs baseline: 5.1357x; 1.0332x over previous
#include <cuda_runtime.h>
#include <cuda_fp16.h>
#include <cstdint>

#define B_    4
#define C_    256
#define CE    128
#define W_    180
#define WS_   18
#define HW_   32400
#define NTOK  324
#define NWIN  400
#define MP2   384          // padded tokens per window

// Scratch (device globals — no allocation allowed)
__device__ __half g_Xw[(size_t)NWIN * MP2 * C_];   // [w][m][c]   (c contiguous)
__device__ __half g_Xc[(size_t)NWIN * C_ * MP2];   // [w][c][m]   (m contiguous)
__device__ __half g_Ewh[(size_t)NWIN * MP2 * C_];  // [w][m][chan] 0..127 theta, 128..255 phi
__device__ __half g_Yh[(size_t)B_ * HW_ * C_];     // [b][hw][c]
__device__ __half g_wh[512 * 256];                 // 0..255 [w_theta;w_phi], 256..511 w_proj

__device__ __forceinline__ void mma16(float* d, const uint32_t* a, const uint32_t* b) {
    asm volatile("mma.sync.aligned.m16n8k16.row.col.f32.f16.f16.f32 "
        "{%0,%1,%2,%3}, {%4,%5,%6,%7}, {%8,%9}, {%0,%1,%2,%3};"
        : "+f"(d[0]), "+f"(d[1]), "+f"(d[2]), "+f"(d[3])
        : "r"(a[0]), "r"(a[1]), "r"(a[2]), "r"(a[3]), "r"(b[0]), "r"(b[1]));
}
__device__ __forceinline__ void ldsm4(uint32_t* r, uint32_t addr) {
    asm volatile("ldmatrix.sync.aligned.m8n8.x4.shared.b16 {%0,%1,%2,%3}, [%4];"
        : "=r"(r[0]), "=r"(r[1]), "=r"(r[2]), "=r"(r[3]) : "r"(addr));
}
__device__ __forceinline__ uint32_t pack2(float a, float b) {
    __half2 h = __floats2half2_rn(a, b);
    return *(uint32_t*)&h;
}
__device__ __forceinline__ void cp16h(uint32_t dst, const __half* src) {
    asm volatile("cp.async.cg.shared.global [%0], [%1], 16;" :: "r"(dst), "l"(src));
}
__device__ __forceinline__ void cp16p(uint32_t dst, const __half* src, bool v) {
    asm volatile("cp.async.cg.shared.global [%0], [%1], 16, %2;"
                 :: "r"(dst), "l"(src), "r"(v ? 16 : 0));
}
#define CP_COMMIT() asm volatile("cp.async.commit_group;")

// A-frag (16x16): rows lane&15, col half-offset (lane>>4)*8.
// Paired B-frags (two 8-row tiles x16): row (lane&7)+((lane>>4)&1)*8 within 16,
//   col half-offset lane&8. r0,r1 = tile0 frag; r2,r3 = tile1 frag.

// ---------------------------------------------------------------------------
// Prep: x -> Xw[w][m][c], Xc[w][c][m] (half, zero-padded m>=324); weights -> wh.
// ---------------------------------------------------------------------------
__global__ __launch_bounds__(256) void k_prep(
    const float* __restrict__ x, const float* __restrict__ wt,
    const float* __restrict__ wp, const float* __restrict__ wj)
{
    __shared__ __half sT[64][384];
    const int blk = blockIdx.x, tid = threadIdx.x;
    if (blk >= NWIN) {
        int wb = blk - NWIN;
        for (int idx = tid; idx < 32768; idx += 256) {
            int row = wb * 128 + (idx >> 8), c = idx & 255;
            float v;
            if (row < 128)      v = wt[row * 256 + c];
            else if (row < 256) v = wp[(row - 128) * 256 + c];
            else                v = wj[(row - 256) * 256 + c];
            g_wh[row * 256 + c] = __float2half(v);
        }
        return;
    }
    const int w = blk, b = w / 100, ih = (w / 10) % 10, iw = w % 10;
    const int hwBase = ih * WS_ * W_ + iw * WS_;
    const int lane = tid & 31, wid = tid >> 5;
    __half* Xw = g_Xw + (size_t)w * MP2 * C_;
    __half* Xc = g_Xc + (size_t)w * C_ * MP2;

    for (int c0 = 0; c0 < C_; c0 += 64) {
        for (int l = 0; l < 8; l++) {
            int ci = wid + l * 8;
            const float* xs = x + (size_t)(b * C_ + c0 + ci) * HW_ + hwBase;
            for (int m = lane; m < MP2; m += 32) {
                float v = 0.f;
                if (m < NTOK) v = xs[(m / WS_) * W_ + m % WS_];
                sT[ci][m] = __float2half(v);
            }
        }
        __syncthreads();
        {   // Xw[m][c]
            int cj = lane * 2;
            for (int m = (tid >> 5); m < MP2; m += 8) {
                uint32_t v = ((uint32_t)__half_as_ushort(sT[cj + 1][m]) << 16)
                           | (uint32_t)__half_as_ushort(sT[cj][m]);
                *(uint32_t*)&Xw[(size_t)m * C_ + c0 + cj] = v;
            }
        }
        for (int l = 0; l < 8; l++) {   // Xc[c][m]
            int ci = (tid >> 5) + l * 8;
            for (int mm = lane * 4; mm < MP2; mm += 128)
                *(uint64_t*)&Xc[(size_t)(c0 + ci) * MP2 + mm] =
                    *(const uint64_t*)&sT[ci][mm];
        }
        __syncthreads();
    }
}

// ---------------------------------------------------------------------------
// pw0: E'[m][e] = Xw[m][c] @ wh[e][c]^T per window. BM=64 m, BN=256 e, K=256.
// ---------------------------------------------------------------------------
#define PW0_SMEM ((2 * 64 * 40 + 2 * 256 * 40) * 2)

__global__ __launch_bounds__(256, 2) void k_pw0()
{
    extern __shared__ __half ps[];
    __half* sA = ps;                  // [2][64][40]
    __half* sB = ps + 2 * 64 * 40;    // [2][256][40]
    const int w = blockIdx.y, mBase = blockIdx.x * 64;
    const int tid = threadIdx.x, lane = tid & 31, wid = tid >> 5;
    const int wm = (wid >> 1) * 16, we = (wid & 1) * 128;
    const int gr = lane >> 2, gc = lane & 3;
    const int lrA = lane & 15, lcA = (lane >> 4) * 8;
    const int lrB = (lane & 7) + ((lane >> 4) & 1) * 8, lcB = lane & 8;
    const __half* Xw = g_Xw + (size_t)w * MP2 * C_ + (size_t)mBase * C_;
    const uint32_t aB = (uint32_t)__cvta_generic_to_shared(sA);
    const uint32_t bB = (uint32_t)__cvta_generic_to_shared(sB);

    auto issue = [&](int s, int k0) {
        {
            int r = tid >> 2, ch = (tid & 3) * 8;
            cp16h(aB + (uint32_t)(s * 2560 + r * 40 + ch) * 2,
                  Xw + (size_t)r * C_ + k0 + ch);
        }
        #pragma unroll
        for (int l = 0; l < 4; l++) {
            int idx = tid + l * 256;
            int e = idx >> 2, ch = (idx & 3) * 8;
            cp16h(bB + (uint32_t)(s * 10240 + e * 40 + ch) * 2,
                  g_wh + e * 256 + k0 + ch);
        }
        CP_COMMIT();
    };

    float acc[16][4] = {};
    issue(0, 0);
    for (int it = 0; it < 8; it++) {
        if (it < 7) { issue((it + 1) & 1, (it + 1) * 32);
                      asm volatile("cp.async.wait_group 1;"); }
        else        { asm volatile("cp.async.wait_group 0;"); }
        __syncthreads();
        const uint32_t aSh = aB + (uint32_t)((it & 1) * 2560) * 2;
        const uint32_t bSh = bB + (uint32_t)((it & 1) * 10240) * 2;
        #pragma unroll
        for (int ks = 0; ks < 2; ks++) {
            int kk = ks * 16;
            uint32_t a[4];
            ldsm4(a, aSh + (uint32_t)((wm + lrA) * 40 + kk + lcA) * 2);
            #pragma unroll
            for (int pt = 0; pt < 8; pt++) {
                uint32_t bp[4];
                ldsm4(bp, bSh + (uint32_t)((we + pt * 16 + lrB) * 40 + kk + lcB) * 2);
                mma16(acc[pt * 2], a, bp);
                mma16(acc[pt * 2 + 1], a, bp + 2);
            }
        }
        __syncthreads();
    }

    __half* Eo = g_Ewh + (size_t)w * MP2 * C_;
    int m0r = mBase + wm + gr;
    #pragma unroll
    for (int et = 0; et < 16; et++) {
        int e = we + et * 8 + 2 * gc;
        *(uint32_t*)&Eo[(size_t)m0r * C_ + e]       = pack2(acc[et][0], acc[et][1]);
        *(uint32_t*)&Eo[(size_t)(m0r + 8) * C_ + e] = pack2(acc[et][2], acc[et][3]);
    }
}

// ---------------------------------------------------------------------------
// Fused attention (fp16 + ldmatrix): CTA = (window, 64-query tile), 256 thr.
// ---------------------------------------------------------------------------
#define FA_SMEM_B (17408 + 17408 + 40960 + 5120 + 512)

__global__ __launch_bounds__(256, 2) void k_fattn()
{
    extern __shared__ __half fs[];
    __half* sTh  = fs;                    // [64][136]
    __half* sPhi = sTh + 64 * 136;        // [2][32][136]
    __half* sG   = sPhi + 2 * 32 * 136;   // [2][256][40]
    __half* sF   = sG + 2 * 256 * 40;     // [64][40]
    float*  sSum = (float*)(sF + 64 * 40);  // [64]
    float*  sInv = sSum + 64;               // [64]

    const int w = blockIdx.y, nBase = blockIdx.x * 64;
    const int b = w / 100, ih = (w / 10) % 10, iw = w % 10;
    const int tid = threadIdx.x, lane = tid & 31, wid = tid >> 5;
    const int gr = lane >> 2, gc = lane & 3;
    const int wn = (wid >> 1) * 16;     // n-range, both phases
    const int wmS = (wid & 1) * 16;     // S-phase m
    const int wcY = (wid & 1) * 128;    // Y-phase c
    const int lrA = lane & 15, lcA = (lane >> 4) * 8;
    const int lrB = (lane & 7) + ((lane >> 4) & 1) * 8, lcB = lane & 8;
    const __half* Eww = g_Ewh + (size_t)w * MP2 * C_;
    const __half* Xc  = g_Xc + (size_t)w * C_ * MP2;
    const float SC = 0.08838834764831843f;  // 1/sqrt(128)
    const uint32_t thB = (uint32_t)__cvta_generic_to_shared(sTh);
    const uint32_t phB = (uint32_t)__cvta_generic_to_shared(sPhi);
    const uint32_t gBB = (uint32_t)__cvta_generic_to_shared(sG);
    const uint32_t fB  = (uint32_t)__cvta_generic_to_shared(sF);

    if (tid < 64) sSum[tid] = 0.f;

    // theta once: sTh[n][e]
    #pragma unroll
    for (int l = 0; l < 4; l++) {
        int idx = tid + l * 256;
        int n = idx >> 4, ch = (idx & 15) * 8;
        cp16h(thB + (uint32_t)(n * 136 + ch) * 2, Eww + (size_t)(nBase + n) * C_ + ch);
    }

    auto issue = [&](int s, int m0) {
        #pragma unroll
        for (int l = 0; l < 2; l++) {
            int idx = tid + l * 256;
            int m = idx >> 4, ch = (idx & 15) * 8;
            cp16h(phB + (uint32_t)((s * 32 + m) * 136 + ch) * 2,
                  Eww + (size_t)(m0 + m) * C_ + CE + ch);
        }
        #pragma unroll
        for (int l = 0; l < 4; l++) {
            int idx = tid + l * 256;
            int c = idx >> 2, ch = (idx & 3) * 8;
            cp16h(gBB + (uint32_t)((s * 256 + c) * 40 + ch) * 2,
                  Xc + (size_t)c * MP2 + m0 + ch);
        }
        CP_COMMIT();
    };

    float yacc[16][4] = {};
    float colp[2] = {};

    issue(0, 0);     // commits theta + buffer 0
    for (int mi = 0; mi < 11; mi++) {
        int m0 = mi * 32;
        if (mi < 10) { issue((mi + 1) & 1, m0 + 32);
                       asm volatile("cp.async.wait_group 1;"); }
        else         { asm volatile("cp.async.wait_group 0;"); }
        __syncthreads();
        const uint32_t phSh = phB + (uint32_t)((mi & 1) * 32 * 136) * 2;
        const uint32_t gSh  = gBB + (uint32_t)((mi & 1) * 256 * 40) * 2;

        // S': A=theta[n][e], B=phi[m][e]
        float sacc[2][4] = {};
        #pragma unroll
        for (int ks = 0; ks < 8; ks++) {
            int kk = ks * 16;
            uint32_t a[4], bp[4];
            ldsm4(a, thB + (uint32_t)((wn + lrA) * 136 + kk + lcA) * 2);
            ldsm4(bp, phSh + (uint32_t)((wmS + lrB) * 136 + kk + lcB) * 2);
            mma16(sacc[0], a, bp);
            mma16(sacc[1], a, bp + 2);
        }
        // exp + mask + sF[n][m] + colsum partials
        #pragma unroll
        for (int t = 0; t < 2; t++) {
            int mg = m0 + wmS + t * 8 + 2 * gc;
            bool v = mg < NTOK;
            float e0 = v ? __expf(sacc[t][0] * SC) : 0.f;
            float e1 = v ? __expf(sacc[t][1] * SC) : 0.f;
            float e2 = v ? __expf(sacc[t][2] * SC) : 0.f;
            float e3 = v ? __expf(sacc[t][3] * SC) : 0.f;
            colp[0] += e0 + e1;
            colp[1] += e2 + e3;
            *(uint32_t*)&sF[(wn + gr) * 40 + wmS + t * 8 + 2 * gc]     = pack2(e0, e1);
            *(uint32_t*)&sF[(wn + gr + 8) * 40 + wmS + t * 8 + 2 * gc] = pack2(e2, e3);
        }
        __syncthreads();

        // Y': A=F'[n][m], B=G[c][m]
        #pragma unroll
        for (int ks = 0; ks < 2; ks++) {
            int kk = ks * 16;
            uint32_t a[4];
            ldsm4(a, fB + (uint32_t)((wn + lrA) * 40 + kk + lcA) * 2);
            #pragma unroll
            for (int pt = 0; pt < 8; pt++) {
                uint32_t bp[4];
                ldsm4(bp, gSh + (uint32_t)((wcY + pt * 16 + lrB) * 40 + kk + lcB) * 2);
                mma16(yacc[pt * 2], a, bp);
                mma16(yacc[pt * 2 + 1], a, bp + 2);
            }
        }
        __syncthreads();
    }

    // column sums (over m) per n
    colp[0] += __shfl_xor_sync(0xffffffffu, colp[0], 1);
    colp[0] += __shfl_xor_sync(0xffffffffu, colp[0], 2);
    colp[1] += __shfl_xor_sync(0xffffffffu, colp[1], 1);
    colp[1] += __shfl_xor_sync(0xffffffffu, colp[1], 2);
    if (gc == 0) {
        atomicAdd(&sSum[wn + gr], colp[0]);
        atomicAdd(&sSum[wn + gr + 8], colp[1]);
    }
    __syncthreads();
    if (tid < 64) sInv[tid] = 1.f / sSum[tid];
    __syncthreads();

    // scale + store Yh[b][hw][c]
    const int hwBase = ih * WS_ * W_ + iw * WS_;
    __half* Yb = g_Yh + (size_t)b * HW_ * C_;
    int n0 = nBase + wn + gr, n1 = n0 + 8;
    bool v0 = n0 < NTOK, v1 = n1 < NTOK;
    float i0 = sInv[wn + gr], i1 = sInv[wn + gr + 8];
    size_t r0 = v0 ? (size_t)(hwBase + (n0 / WS_) * W_ + n0 % WS_) * C_ : 0;
    size_t r1 = v1 ? (size_t)(hwBase + (n1 / WS_) * W_ + n1 % WS_) * C_ : 0;
    #pragma unroll
    for (int ct = 0; ct < 16; ct++) {
        int c = wcY + ct * 8 + 2 * gc;
        if (v0) *(uint32_t*)&Yb[r0 + c] = pack2(yacc[ct][0] * i0, yacc[ct][1] * i0);
        if (v1) *(uint32_t*)&Yb[r1 + c] = pack2(yacc[ct][2] * i1, yacc[ct][3] * i1);
    }
}

// ---------------------------------------------------------------------------
// pw1: out[o][p] = x + wproj[o][c] @ Yh[p][c]^T. BM=128 o, BN=128 p, K=256.
// ---------------------------------------------------------------------------
__global__ __launch_bounds__(256, 2) void k_pw1(
    const float* __restrict__ x, float* __restrict__ out)
{
    __shared__ __half sA[2][128][40];
    __shared__ __half sB[2][128][40];
    const int b = blockIdx.z, oBase = blockIdx.y * 128, pBase = blockIdx.x * 128;
    const int tid = threadIdx.x, lane = tid & 31, wid = tid >> 5;
    const int wo = (wid >> 2) * 64, wp = (wid & 3) * 32;
    const int gr = lane >> 2, gc = lane & 3;
    const int lrA = lane & 15, lcA = (lane >> 4) * 8;
    const int lrB = (lane & 7) + ((lane >> 4) & 1) * 8, lcB = lane & 8;
    const __half* Yb = g_Yh + (size_t)b * HW_ * C_;
    const uint32_t aB = (uint32_t)__cvta_generic_to_shared(&sA[0][0][0]);
    const uint32_t bB = (uint32_t)__cvta_generic_to_shared(&sB[0][0][0]);

    auto issue = [&](int s, int k0) {
        #pragma unroll
        for (int l = 0; l < 2; l++) {
            int idx = tid + l * 256;
            int r = idx >> 2, ch = (idx & 3) * 8;
            cp16h(aB + (uint32_t)(s * 5120 + r * 40 + ch) * 2,
                  g_wh + (256 + oBase + r) * 256 + k0 + ch);
        }
        #pragma unroll
        for (int l = 0; l < 2; l++) {
            int idx = tid + l * 256;
            int p = idx >> 2, ch = (idx & 3) * 8;
            int pg = pBase + p;
            bool v = pg < HW_;
            cp16p(bB + (uint32_t)(s * 5120 + p * 40 + ch) * 2,
                  Yb + (size_t)(v ? pg : 0) * C_ + k0 + ch, v);
        }
        CP_COMMIT();
    };

    float acc[4][4][4] = {};
    issue(0, 0);
    for (int it = 0; it < 8; it++) {
        if (it < 7) { issue((it + 1) & 1, (it + 1) * 32);
                      asm volatile("cp.async.wait_group 1;"); }
        else        { asm volatile("cp.async.wait_group 0;"); }
        __syncthreads();
        const uint32_t aSh = aB + (uint32_t)((it & 1) * 5120) * 2;
        const uint32_t bSh = bB + (uint32_t)((it & 1) * 5120) * 2;
        #pragma unroll
        for (int ks = 0; ks < 2; ks++) {
            int kk = ks * 16;
            uint32_t a[4][4];
            #pragma unroll
            for (int ot = 0; ot < 4; ot++)
                ldsm4(a[ot], aSh + (uint32_t)((wo + ot * 16 + lrA) * 40 + kk + lcA) * 2);
            #pragma unroll
            for (int pp = 0; pp < 2; pp++) {
                uint32_t bp[4];
                ldsm4(bp, bSh + (uint32_t)((wp + pp * 16 + lrB) * 40 + kk + lcB) * 2);
                #pragma unroll
                for (int ot = 0; ot < 4; ot++) {
                    mma16(acc[ot][pp * 2], a[ot], bp);
                    mma16(acc[ot][pp * 2 + 1], a[ot], bp + 2);
                }
            }
        }
        __syncthreads();
    }

    #pragma unroll
    for (int ot = 0; ot < 4; ot++) {
        int o0 = oBase + wo + ot * 16 + gr;
        size_t row0 = ((size_t)b * C_ + o0) * HW_;
        size_t row1 = ((size_t)b * C_ + o0 + 8) * HW_;
        #pragma unroll
        for (int pt = 0; pt < 4; pt++) {
            int p = pBase + wp + pt * 8 + 2 * gc;
            if (p < HW_) {
                float2 r0 = *(const float2*)&x[row0 + p];
                float2 r1 = *(const float2*)&x[row1 + p];
                *(float2*)&out[row0 + p] =
                    make_float2(acc[ot][pt][0] + r0.x, acc[ot][pt][1] + r0.y);
                *(float2*)&out[row1 + p] =
                    make_float2(acc[ot][pt][2] + r1.x, acc[ot][pt][3] + r1.y);
            }
        }
    }
}

// ---------------------------------------------------------------------------
extern "C" void kernel_launch(void* const* d_in, const int* in_sizes, int n_in,
                              void* d_out, int out_size)
{
    const float* x       = (const float*)d_in[0];
    const float* w_theta = (const float*)d_in[1];
    const float* w_phi   = (const float*)d_in[2];
    const float* w_proj  = (const float*)d_in[3];
    float* out = (float*)d_out;

    cudaFuncSetAttribute(k_pw0, cudaFuncAttributeMaxDynamicSharedMemorySize, PW0_SMEM);
    cudaFuncSetAttribute(k_fattn, cudaFuncAttributeMaxDynamicSharedMemorySize, FA_SMEM_B);

    // 1) convert x (two layouts) + weights to half
    k_prep<<<NWIN + 4, 256>>>(x, w_theta, w_phi, w_proj);
    // 2) embeddings -> Ewh[w][m][chan]
    dim3 g0(6, NWIN);
    k_pw0<<<g0, 256, PW0_SMEM>>>();
    // 3) fused attention -> Yh[b][hw][c]
    dim3 gf(6, NWIN);
    k_fattn<<<gf, 256, FA_SMEM_B>>>();
    // 4) out = x + w_proj @ Y
    dim3 g1(254, 2, B_);
    k_pw1<<<g1, 256>>>(x, out);
}

// round 8
// speedup vs baseline: 5.1392x; 1.0007x over previous
#include <cuda_runtime.h>
#include <cuda_fp16.h>
#include <cstdint>

#define B_    4
#define C_    256
#define CE    128
#define W_    180
#define WS_   18
#define HW_   32400
#define NTOK  324
#define NWIN  400
#define MP2   384          // padded tokens per window

// Scratch (device globals — no allocation allowed)
__device__ __half g_Xw[(size_t)NWIN * MP2 * C_];   // [w][m][c]   (c contiguous)
__device__ __half g_Xc[(size_t)NWIN * C_ * MP2];   // [w][c][m]   (m contiguous)
__device__ __half g_Ewh[(size_t)NWIN * MP2 * C_];  // [w][m][chan] 0..127 theta, 128..255 phi
__device__ __half g_Yh[(size_t)B_ * HW_ * C_];     // [b][hw][c]
__device__ __half g_wh[512 * 256];                 // 0..255 [w_theta;w_phi], 256..511 w_proj

__device__ __forceinline__ void mma16(float* d, const uint32_t* a, const uint32_t* b) {
    asm volatile("mma.sync.aligned.m16n8k16.row.col.f32.f16.f16.f32 "
        "{%0,%1,%2,%3}, {%4,%5,%6,%7}, {%8,%9}, {%0,%1,%2,%3};"
        : "+f"(d[0]), "+f"(d[1]), "+f"(d[2]), "+f"(d[3])
        : "r"(a[0]), "r"(a[1]), "r"(a[2]), "r"(a[3]), "r"(b[0]), "r"(b[1]));
}
__device__ __forceinline__ void ldsm4(uint32_t* r, uint32_t addr) {
    asm volatile("ldmatrix.sync.aligned.m8n8.x4.shared.b16 {%0,%1,%2,%3}, [%4];"
        : "=r"(r[0]), "=r"(r[1]), "=r"(r[2]), "=r"(r[3]) : "r"(addr));
}
__device__ __forceinline__ uint32_t pack2(float a, float b) {
    __half2 h = __floats2half2_rn(a, b);
    return *(uint32_t*)&h;
}
__device__ __forceinline__ void cp16h(uint32_t dst, const __half* src) {
    asm volatile("cp.async.cg.shared.global [%0], [%1], 16;" :: "r"(dst), "l"(src));
}
__device__ __forceinline__ void cp16p(uint32_t dst, const __half* src, bool v) {
    asm volatile("cp.async.cg.shared.global [%0], [%1], 16, %2;"
                 :: "r"(dst), "l"(src), "r"(v ? 16 : 0));
}
#define CP_COMMIT() asm volatile("cp.async.commit_group;")
#define CP_WAIT(N)  asm volatile("cp.async.wait_group %0;" :: "n"(N))

// ---------------------------------------------------------------------------
// Prep: x -> Xw[w][m][c], Xc[w][c][m] (half, zero-padded m>=324); weights -> wh.
// ---------------------------------------------------------------------------
__global__ __launch_bounds__(256) void k_prep(
    const float* __restrict__ x, const float* __restrict__ wt,
    const float* __restrict__ wp, const float* __restrict__ wj)
{
    __shared__ __half sT[64][384];
    const int blk = blockIdx.x, tid = threadIdx.x;
    if (blk >= NWIN) {
        int wb = blk - NWIN;
        for (int idx = tid; idx < 32768; idx += 256) {
            int row = wb * 128 + (idx >> 8), c = idx & 255;
            float v;
            if (row < 128)      v = wt[row * 256 + c];
            else if (row < 256) v = wp[(row - 128) * 256 + c];
            else                v = wj[(row - 256) * 256 + c];
            g_wh[row * 256 + c] = __float2half(v);
        }
        return;
    }
    const int w = blk, b = w / 100, ih = (w / 10) % 10, iw = w % 10;
    const int hwBase = ih * WS_ * W_ + iw * WS_;
    const int lane = tid & 31, wid = tid >> 5;
    __half* Xw = g_Xw + (size_t)w * MP2 * C_;
    __half* Xc = g_Xc + (size_t)w * C_ * MP2;

    for (int c0 = 0; c0 < C_; c0 += 64) {
        for (int l = 0; l < 8; l++) {
            int ci = wid + l * 8;
            const float* xs = x + (size_t)(b * C_ + c0 + ci) * HW_ + hwBase;
            for (int m = lane; m < MP2; m += 32) {
                float v = 0.f;
                if (m < NTOK) v = xs[(m / WS_) * W_ + m % WS_];
                sT[ci][m] = __float2half(v);
            }
        }
        __syncthreads();
        {   // Xw[m][c]
            int cj = lane * 2;
            for (int m = (tid >> 5); m < MP2; m += 8) {
                uint32_t v = ((uint32_t)__half_as_ushort(sT[cj + 1][m]) << 16)
                           | (uint32_t)__half_as_ushort(sT[cj][m]);
                *(uint32_t*)&Xw[(size_t)m * C_ + c0 + cj] = v;
            }
        }
        for (int l = 0; l < 8; l++) {   // Xc[c][m]
            int ci = (tid >> 5) + l * 8;
            for (int mm = lane * 4; mm < MP2; mm += 128)
                *(uint64_t*)&Xc[(size_t)(c0 + ci) * MP2 + mm] =
                    *(const uint64_t*)&sT[ci][mm];
        }
        __syncthreads();
    }
}

// ---------------------------------------------------------------------------
// pw0: E'[m][e] = Xw[m][c] @ wh[e][c]^T per window. BM=64 m, BN=256 e, K=256.
// 3-stage cp.async ring, 1 syncthreads/iter.
// ---------------------------------------------------------------------------
#define PW0_SMEM ((3 * 64 * 40 + 3 * 256 * 40) * 2)

__global__ __launch_bounds__(256, 2) void k_pw0()
{
    extern __shared__ __half ps[];
    __half* sA = ps;                  // [3][64][40]
    __half* sB = ps + 3 * 64 * 40;    // [3][256][40]
    const int w = blockIdx.y, mBase = blockIdx.x * 64;
    const int tid = threadIdx.x, lane = tid & 31, wid = tid >> 5;
    const int wm = (wid >> 1) * 16, we = (wid & 1) * 128;
    const int gr = lane >> 2, gc = lane & 3;
    const int lrA = lane & 15, lcA = (lane >> 4) * 8;
    const int lrB = (lane & 7) + ((lane >> 4) & 1) * 8, lcB = lane & 8;
    const __half* Xw = g_Xw + (size_t)w * MP2 * C_ + (size_t)mBase * C_;
    const uint32_t aB = (uint32_t)__cvta_generic_to_shared(sA);
    const uint32_t bB = (uint32_t)__cvta_generic_to_shared(sB);

    auto issue = [&](int s, int k0) {
        {
            int r = tid >> 2, ch = (tid & 3) * 8;
            cp16h(aB + (uint32_t)(s * 2560 + r * 40 + ch) * 2,
                  Xw + (size_t)r * C_ + k0 + ch);
        }
        #pragma unroll
        for (int l = 0; l < 4; l++) {
            int idx = tid + l * 256;
            int e = idx >> 2, ch = (idx & 3) * 8;
            cp16h(bB + (uint32_t)(s * 10240 + e * 40 + ch) * 2,
                  g_wh + e * 256 + k0 + ch);
        }
        CP_COMMIT();
    };

    float acc[16][4] = {};
    issue(0, 0); issue(1, 32);
    CP_WAIT(1);
    __syncthreads();
    for (int it = 0; it < 8; it++) {
        if (it < 6) issue((it + 2) % 3, (it + 2) * 32);
        const uint32_t aSh = aB + (uint32_t)((it % 3) * 2560) * 2;
        const uint32_t bSh = bB + (uint32_t)((it % 3) * 10240) * 2;
        #pragma unroll
        for (int ks = 0; ks < 2; ks++) {
            int kk = ks * 16;
            uint32_t a[4];
            ldsm4(a, aSh + (uint32_t)((wm + lrA) * 40 + kk + lcA) * 2);
            #pragma unroll
            for (int pt = 0; pt < 8; pt++) {
                uint32_t bp[4];
                ldsm4(bp, bSh + (uint32_t)((we + pt * 16 + lrB) * 40 + kk + lcB) * 2);
                mma16(acc[pt * 2], a, bp);
                mma16(acc[pt * 2 + 1], a, bp + 2);
            }
        }
        if (it < 6)      { CP_WAIT(1); __syncthreads(); }
        else if (it < 7) { CP_WAIT(0); __syncthreads(); }
    }

    __half* Eo = g_Ewh + (size_t)w * MP2 * C_;
    int m0r = mBase + wm + gr;
    #pragma unroll
    for (int et = 0; et < 16; et++) {
        int e = we + et * 8 + 2 * gc;
        *(uint32_t*)&Eo[(size_t)m0r * C_ + e]       = pack2(acc[et][0], acc[et][1]);
        *(uint32_t*)&Eo[(size_t)(m0r + 8) * C_ + e] = pack2(acc[et][2], acc[et][3]);
    }
}

// ---------------------------------------------------------------------------
// Fused attention (fp16 + ldmatrix + 3-stage ring): CTA = (window, 64 queries).
// ---------------------------------------------------------------------------
#define FA_SMEM_B (17408 + 3 * 8704 + 3 * 20480 + 5120 + 512)

__global__ __launch_bounds__(256, 2) void k_fattn()
{
    extern __shared__ __half fs[];
    __half* sTh  = fs;                    // [64][136]
    __half* sPhi = sTh + 64 * 136;        // [3][32][136]
    __half* sG   = sPhi + 3 * 32 * 136;   // [3][256][40]
    __half* sF   = sG + 3 * 256 * 40;     // [64][40]
    float*  sSum = (float*)(sF + 64 * 40);  // [64]
    float*  sInv = sSum + 64;               // [64]

    const int w = blockIdx.y, nBase = blockIdx.x * 64;
    const int b = w / 100, ih = (w / 10) % 10, iw = w % 10;
    const int tid = threadIdx.x, lane = tid & 31, wid = tid >> 5;
    const int gr = lane >> 2, gc = lane & 3;
    const int wn = (wid >> 1) * 16;     // n-range, both phases
    const int wmS = (wid & 1) * 16;     // S-phase m
    const int wcY = (wid & 1) * 128;    // Y-phase c
    const int lrA = lane & 15, lcA = (lane >> 4) * 8;
    const int lrB = (lane & 7) + ((lane >> 4) & 1) * 8, lcB = lane & 8;
    const __half* Eww = g_Ewh + (size_t)w * MP2 * C_;
    const __half* Xc  = g_Xc + (size_t)w * C_ * MP2;
    const float SC = 0.08838834764831843f;  // 1/sqrt(128)
    const uint32_t thB = (uint32_t)__cvta_generic_to_shared(sTh);
    const uint32_t phB = (uint32_t)__cvta_generic_to_shared(sPhi);
    const uint32_t gBB = (uint32_t)__cvta_generic_to_shared(sG);
    const uint32_t fB  = (uint32_t)__cvta_generic_to_shared(sF);

    if (tid < 64) sSum[tid] = 0.f;

    // theta once: sTh[n][e] (committed with group 0)
    #pragma unroll
    for (int l = 0; l < 4; l++) {
        int idx = tid + l * 256;
        int n = idx >> 4, ch = (idx & 15) * 8;
        cp16h(thB + (uint32_t)(n * 136 + ch) * 2, Eww + (size_t)(nBase + n) * C_ + ch);
    }

    auto issue = [&](int s, int m0) {
        #pragma unroll
        for (int l = 0; l < 2; l++) {
            int idx = tid + l * 256;
            int m = idx >> 4, ch = (idx & 15) * 8;
            cp16h(phB + (uint32_t)((s * 32 + m) * 136 + ch) * 2,
                  Eww + (size_t)(m0 + m) * C_ + CE + ch);
        }
        #pragma unroll
        for (int l = 0; l < 4; l++) {
            int idx = tid + l * 256;
            int c = idx >> 2, ch = (idx & 3) * 8;
            cp16h(gBB + (uint32_t)((s * 256 + c) * 40 + ch) * 2,
                  Xc + (size_t)c * MP2 + m0 + ch);
        }
        CP_COMMIT();
    };

    float yacc[16][4] = {};
    float colp[2] = {};

    issue(0, 0); issue(1, 32);
    CP_WAIT(1);
    __syncthreads();   // slot 0 ready; also covers sSum init

    for (int mi = 0; mi < 11; mi++) {
        int m0 = mi * 32;
        if (mi < 9) issue((mi + 2) % 3, (mi + 2) * 32);
        const uint32_t phSh = phB + (uint32_t)((mi % 3) * 32 * 136) * 2;
        const uint32_t gSh  = gBB + (uint32_t)((mi % 3) * 256 * 40) * 2;

        // S': A=theta[n][e], B=phi[m][e]
        float sacc[2][4] = {};
        #pragma unroll
        for (int ks = 0; ks < 8; ks++) {
            int kk = ks * 16;
            uint32_t a[4], bp[4];
            ldsm4(a, thB + (uint32_t)((wn + lrA) * 136 + kk + lcA) * 2);
            ldsm4(bp, phSh + (uint32_t)((wmS + lrB) * 136 + kk + lcB) * 2);
            mma16(sacc[0], a, bp);
            mma16(sacc[1], a, bp + 2);
        }
        // exp + mask + sF[n][m] + colsum partials
        #pragma unroll
        for (int t = 0; t < 2; t++) {
            int mg = m0 + wmS + t * 8 + 2 * gc;
            bool v = mg < NTOK;
            float e0 = v ? __expf(sacc[t][0] * SC) : 0.f;
            float e1 = v ? __expf(sacc[t][1] * SC) : 0.f;
            float e2 = v ? __expf(sacc[t][2] * SC) : 0.f;
            float e3 = v ? __expf(sacc[t][3] * SC) : 0.f;
            colp[0] += e0 + e1;
            colp[1] += e2 + e3;
            *(uint32_t*)&sF[(wn + gr) * 40 + wmS + t * 8 + 2 * gc]     = pack2(e0, e1);
            *(uint32_t*)&sF[(wn + gr + 8) * 40 + wmS + t * 8 + 2 * gc] = pack2(e2, e3);
        }
        __syncthreads();

        // Y': A=F'[n][m], B=G[c][m]
        #pragma unroll
        for (int ks = 0; ks < 2; ks++) {
            int kk = ks * 16;
            uint32_t a[4];
            ldsm4(a, fB + (uint32_t)((wn + lrA) * 40 + kk + lcA) * 2);
            #pragma unroll
            for (int pt = 0; pt < 8; pt++) {
                uint32_t bp[4];
                ldsm4(bp, gSh + (uint32_t)((wcY + pt * 16 + lrB) * 40 + kk + lcB) * 2);
                mma16(yacc[pt * 2], a, bp);
                mma16(yacc[pt * 2 + 1], a, bp + 2);
            }
        }
        if (mi < 9)       { CP_WAIT(1); __syncthreads(); }
        else if (mi < 10) { CP_WAIT(0); __syncthreads(); }
    }
    __syncthreads();   // sF/yacc reads done before colsum reuse of sSum

    // column sums (over m) per n
    colp[0] += __shfl_xor_sync(0xffffffffu, colp[0], 1);
    colp[0] += __shfl_xor_sync(0xffffffffu, colp[0], 2);
    colp[1] += __shfl_xor_sync(0xffffffffu, colp[1], 1);
    colp[1] += __shfl_xor_sync(0xffffffffu, colp[1], 2);
    if (gc == 0) {
        atomicAdd(&sSum[wn + gr], colp[0]);
        atomicAdd(&sSum[wn + gr + 8], colp[1]);
    }
    __syncthreads();
    if (tid < 64) sInv[tid] = 1.f / sSum[tid];
    __syncthreads();

    // scale + store Yh[b][hw][c]
    const int hwBase = ih * WS_ * W_ + iw * WS_;
    __half* Yb = g_Yh + (size_t)b * HW_ * C_;
    int n0 = nBase + wn + gr, n1 = n0 + 8;
    bool v0 = n0 < NTOK, v1 = n1 < NTOK;
    float i0 = sInv[wn + gr], i1 = sInv[wn + gr + 8];
    size_t r0 = v0 ? (size_t)(hwBase + (n0 / WS_) * W_ + n0 % WS_) * C_ : 0;
    size_t r1 = v1 ? (size_t)(hwBase + (n1 / WS_) * W_ + n1 % WS_) * C_ : 0;
    #pragma unroll
    for (int ct = 0; ct < 16; ct++) {
        int c = wcY + ct * 8 + 2 * gc;
        if (v0) *(uint32_t*)&Yb[r0 + c] = pack2(yacc[ct][0] * i0, yacc[ct][1] * i0);
        if (v1) *(uint32_t*)&Yb[r1 + c] = pack2(yacc[ct][2] * i1, yacc[ct][3] * i1);
    }
}

// ---------------------------------------------------------------------------
// pw1: out[o][p] = x + wproj[o][c] @ Yh[p][c]^T. BM=128 o, BN=128 p, K=256.
// 3-stage cp.async ring, 1 syncthreads/iter.
// ---------------------------------------------------------------------------
#define PW1_SMEM ((3 * 128 * 40 + 3 * 128 * 40) * 2)

__global__ __launch_bounds__(256, 2) void k_pw1(
    const float* __restrict__ x, float* __restrict__ out)
{
    extern __shared__ __half qs[];
    __half* sA = qs;                    // [3][128][40]
    __half* sB = qs + 3 * 128 * 40;     // [3][128][40]
    const int b = blockIdx.z, oBase = blockIdx.y * 128, pBase = blockIdx.x * 128;
    const int tid = threadIdx.x, lane = tid & 31, wid = tid >> 5;
    const int wo = (wid >> 2) * 64, wp = (wid & 3) * 32;
    const int gr = lane >> 2, gc = lane & 3;
    const int lrA = lane & 15, lcA = (lane >> 4) * 8;
    const int lrB = (lane & 7) + ((lane >> 4) & 1) * 8, lcB = lane & 8;
    const __half* Yb = g_Yh + (size_t)b * HW_ * C_;
    const uint32_t aB = (uint32_t)__cvta_generic_to_shared(sA);
    const uint32_t bB = (uint32_t)__cvta_generic_to_shared(sB);

    auto issue = [&](int s, int k0) {
        #pragma unroll
        for (int l = 0; l < 2; l++) {
            int idx = tid + l * 256;
            int r = idx >> 2, ch = (idx & 3) * 8;
            cp16h(aB + (uint32_t)(s * 5120 + r * 40 + ch) * 2,
                  g_wh + (256 + oBase + r) * 256 + k0 + ch);
        }
        #pragma unroll
        for (int l = 0; l < 2; l++) {
            int idx = tid + l * 256;
            int p = idx >> 2, ch = (idx & 3) * 8;
            int pg = pBase + p;
            bool v = pg < HW_;
            cp16p(bB + (uint32_t)(s * 5120 + p * 40 + ch) * 2,
                  Yb + (size_t)(v ? pg : 0) * C_ + k0 + ch, v);
        }
        CP_COMMIT();
    };

    float acc[4][4][4] = {};
    issue(0, 0); issue(1, 32);
    CP_WAIT(1);
    __syncthreads();
    for (int it = 0; it < 8; it++) {
        if (it < 6) issue((it + 2) % 3, (it + 2) * 32);
        const uint32_t aSh = aB + (uint32_t)((it % 3) * 5120) * 2;
        const uint32_t bSh = bB + (uint32_t)((it % 3) * 5120) * 2;
        #pragma unroll
        for (int ks = 0; ks < 2; ks++) {
            int kk = ks * 16;
            uint32_t a[4][4];
            #pragma unroll
            for (int ot = 0; ot < 4; ot++)
                ldsm4(a[ot], aSh + (uint32_t)((wo + ot * 16 + lrA) * 40 + kk + lcA) * 2);
            #pragma unroll
            for (int pp = 0; pp < 2; pp++) {
                uint32_t bp[4];
                ldsm4(bp, bSh + (uint32_t)((wp + pp * 16 + lrB) * 40 + kk + lcB) * 2);
                #pragma unroll
                for (int ot = 0; ot < 4; ot++) {
                    mma16(acc[ot][pp * 2], a[ot], bp);
                    mma16(acc[ot][pp * 2 + 1], a[ot], bp + 2);
                }
            }
        }
        if (it < 6)      { CP_WAIT(1); __syncthreads(); }
        else if (it < 7) { CP_WAIT(0); __syncthreads(); }
    }

    #pragma unroll
    for (int ot = 0; ot < 4; ot++) {
        int o0 = oBase + wo + ot * 16 + gr;
        size_t row0 = ((size_t)b * C_ + o0) * HW_;
        size_t row1 = ((size_t)b * C_ + o0 + 8) * HW_;
        #pragma unroll
        for (int pt = 0; pt < 4; pt++) {
            int p = pBase + wp + pt * 8 + 2 * gc;
            if (p < HW_) {
                float2 r0 = *(const float2*)&x[row0 + p];
                float2 r1 = *(const float2*)&x[row1 + p];
                *(float2*)&out[row0 + p] =
                    make_float2(acc[ot][pt][0] + r0.x, acc[ot][pt][1] + r0.y);
                *(float2*)&out[row1 + p] =
                    make_float2(acc[ot][pt][2] + r1.x, acc[ot][pt][3] + r1.y);
            }
        }
    }
}

// ---------------------------------------------------------------------------
extern "C" void kernel_launch(void* const* d_in, const int* in_sizes, int n_in,
                              void* d_out, int out_size)
{
    const float* x       = (const float*)d_in[0];
    const float* w_theta = (const float*)d_in[1];
    const float* w_phi   = (const float*)d_in[2];
    const float* w_proj  = (const float*)d_in[3];
    float* out = (float*)d_out;

    cudaFuncSetAttribute(k_pw0, cudaFuncAttributeMaxDynamicSharedMemorySize, PW0_SMEM);
    cudaFuncSetAttribute(k_fattn, cudaFuncAttributeMaxDynamicSharedMemorySize, FA_SMEM_B);
    cudaFuncSetAttribute(k_pw1, cudaFuncAttributeMaxDynamicSharedMemorySize, PW1_SMEM);

    // 1) convert x (two layouts) + weights to half
    k_prep<<<NWIN + 4, 256>>>(x, w_theta, w_phi, w_proj);
    // 2) embeddings -> Ewh[w][m][chan]
    dim3 g0(6, NWIN);
    k_pw0<<<g0, 256, PW0_SMEM>>>();
    // 3) fused attention -> Yh[b][hw][c]
    dim3 gf(6, NWIN);
    k_fattn<<<gf, 256, FA_SMEM_B>>>();
    // 4) out = x + w_proj @ Y
    dim3 g1(254, 2, B_);
    k_pw1<<<g1, 256, PW1_SMEM>>>(x, out);
}

// round 9
// speedup vs baseline: 5.1766x; 1.0073x over previous
#include <cuda_runtime.h>
#include <cuda_fp16.h>
#include <cstdint>

#define B_    4
#define C_    256
#define CE    128
#define W_    180
#define WS_   18
#define HW_   32400
#define NTOK  324
#define NWIN  400
#define MP2   384          // padded tokens per window

// Scratch (device globals — no allocation allowed)
__device__ __half g_Xw[(size_t)NWIN * MP2 * C_];   // [w][m][c]   (c contiguous)
__device__ __half g_Xc[(size_t)NWIN * C_ * MP2];   // [w][c][m]   (m contiguous)
__device__ __half g_Ewh[(size_t)NWIN * MP2 * C_];  // [w][m][chan] 0..127 theta, 128..255 phi
__device__ __half g_Yh[(size_t)B_ * HW_ * C_];     // [b][hw][c]
__device__ __half g_wh[512 * 256];                 // 0..255 [w_theta;w_phi], 256..511 w_proj

__device__ __forceinline__ void mma16(float* d, const uint32_t* a, const uint32_t* b) {
    asm volatile("mma.sync.aligned.m16n8k16.row.col.f32.f16.f16.f32 "
        "{%0,%1,%2,%3}, {%4,%5,%6,%7}, {%8,%9}, {%0,%1,%2,%3};"
        : "+f"(d[0]), "+f"(d[1]), "+f"(d[2]), "+f"(d[3])
        : "r"(a[0]), "r"(a[1]), "r"(a[2]), "r"(a[3]), "r"(b[0]), "r"(b[1]));
}
__device__ __forceinline__ void ldsm4(uint32_t* r, uint32_t addr) {
    asm volatile("ldmatrix.sync.aligned.m8n8.x4.shared.b16 {%0,%1,%2,%3}, [%4];"
        : "=r"(r[0]), "=r"(r[1]), "=r"(r[2]), "=r"(r[3]) : "r"(addr));
}
__device__ __forceinline__ uint32_t pack2(float a, float b) {
    __half2 h = __floats2half2_rn(a, b);
    return *(uint32_t*)&h;
}
__device__ __forceinline__ void cp16h(uint32_t dst, const __half* src) {
    asm volatile("cp.async.cg.shared.global [%0], [%1], 16;" :: "r"(dst), "l"(src));
}
__device__ __forceinline__ void cp16p(uint32_t dst, const __half* src, bool v) {
    asm volatile("cp.async.cg.shared.global [%0], [%1], 16, %2;"
                 :: "r"(dst), "l"(src), "r"(v ? 16 : 0));
}
#define CP_COMMIT() asm volatile("cp.async.commit_group;")
#define CP_WAIT(N)  asm volatile("cp.async.wait_group %0;" :: "n"(N))

// ---------------------------------------------------------------------------
// Prep: x -> Xw[w][m][c], Xc[w][c][m] (half, zero-padded m>=324); weights -> wh.
// ---------------------------------------------------------------------------
__global__ __launch_bounds__(256) void k_prep(
    const float* __restrict__ x, const float* __restrict__ wt,
    const float* __restrict__ wp, const float* __restrict__ wj)
{
    __shared__ __half sT[64][384];
    const int blk = blockIdx.x, tid = threadIdx.x;
    if (blk >= NWIN) {
        int wb = blk - NWIN;
        for (int idx = tid; idx < 32768; idx += 256) {
            int row = wb * 128 + (idx >> 8), c = idx & 255;
            float v;
            if (row < 128)      v = wt[row * 256 + c];
            else if (row < 256) v = wp[(row - 128) * 256 + c];
            else                v = wj[(row - 256) * 256 + c];
            g_wh[row * 256 + c] = __float2half(v);
        }
        return;
    }
    const int w = blk, b = w / 100, ih = (w / 10) % 10, iw = w % 10;
    const int hwBase = ih * WS_ * W_ + iw * WS_;
    const int lane = tid & 31, wid = tid >> 5;
    __half* Xw = g_Xw + (size_t)w * MP2 * C_;
    __half* Xc = g_Xc + (size_t)w * C_ * MP2;

    for (int c0 = 0; c0 < C_; c0 += 64) {
        for (int l = 0; l < 8; l++) {
            int ci = wid + l * 8;
            const float* xs = x + (size_t)(b * C_ + c0 + ci) * HW_ + hwBase;
            for (int m = lane; m < MP2; m += 32) {
                float v = 0.f;
                if (m < NTOK) v = xs[(m / WS_) * W_ + m % WS_];
                sT[ci][m] = __float2half(v);
            }
        }
        __syncthreads();
        {   // Xw[m][c]
            int cj = lane * 2;
            for (int m = (tid >> 5); m < MP2; m += 8) {
                uint32_t v = ((uint32_t)__half_as_ushort(sT[cj + 1][m]) << 16)
                           | (uint32_t)__half_as_ushort(sT[cj][m]);
                *(uint32_t*)&Xw[(size_t)m * C_ + c0 + cj] = v;
            }
        }
        for (int l = 0; l < 8; l++) {   // Xc[c][m]
            int ci = (tid >> 5) + l * 8;
            for (int mm = lane * 4; mm < MP2; mm += 128)
                *(uint64_t*)&Xc[(size_t)(c0 + ci) * MP2 + mm] =
                    *(const uint64_t*)&sT[ci][mm];
        }
        __syncthreads();
    }
}

// ---------------------------------------------------------------------------
// pw0: E'[m][e] = Xw[m][c] @ wh[e][c]^T. BM=64 m, BN=128 e, K=256, BK=32.
// 8 warps = 2(m) x 4(e): warp 32m x 32e (acc 32). occ 3.
// ---------------------------------------------------------------------------
#define PW0_SMEM ((3 * 64 * 40 + 3 * 128 * 40) * 2)

__global__ __launch_bounds__(256, 3) void k_pw0()
{
    extern __shared__ __half ps[];
    __half* sA = ps;                  // [3][64][40]
    __half* sB = ps + 3 * 64 * 40;    // [3][128][40]
    const int w = blockIdx.z, mBase = blockIdx.x * 64, eBase = blockIdx.y * 128;
    const int tid = threadIdx.x, lane = tid & 31, wid = tid >> 5;
    const int wm = (wid >> 2) * 32, we = (wid & 3) * 32;
    const int gr = lane >> 2, gc = lane & 3;
    const int lrA = lane & 15, lcA = (lane >> 4) * 8;
    const int lrB = (lane & 7) + ((lane >> 4) & 1) * 8, lcB = lane & 8;
    const __half* Xw = g_Xw + (size_t)w * MP2 * C_ + (size_t)mBase * C_;
    const __half* Wsrc = g_wh + eBase * 256;
    const uint32_t aB = (uint32_t)__cvta_generic_to_shared(sA);
    const uint32_t bB = (uint32_t)__cvta_generic_to_shared(sB);

    auto issue = [&](int s, int k0) {
        {
            int r = tid >> 2, ch = (tid & 3) * 8;
            cp16h(aB + (uint32_t)(s * 2560 + r * 40 + ch) * 2,
                  Xw + (size_t)r * C_ + k0 + ch);
        }
        #pragma unroll
        for (int l = 0; l < 2; l++) {
            int idx = tid + l * 256;
            int e = idx >> 2, ch = (idx & 3) * 8;
            cp16h(bB + (uint32_t)(s * 5120 + e * 40 + ch) * 2,
                  Wsrc + e * 256 + k0 + ch);
        }
        CP_COMMIT();
    };

    float acc[2][4][4] = {};
    issue(0, 0); issue(1, 32);
    CP_WAIT(1);
    __syncthreads();
    for (int it = 0; it < 8; it++) {
        if (it < 6) issue((it + 2) % 3, (it + 2) * 32);
        const uint32_t aSh = aB + (uint32_t)((it % 3) * 2560) * 2;
        const uint32_t bSh = bB + (uint32_t)((it % 3) * 5120) * 2;
        #pragma unroll
        for (int ks = 0; ks < 2; ks++) {
            int kk = ks * 16;
            uint32_t a[2][4];
            #pragma unroll
            for (int mt = 0; mt < 2; mt++)
                ldsm4(a[mt], aSh + (uint32_t)((wm + mt * 16 + lrA) * 40 + kk + lcA) * 2);
            #pragma unroll
            for (int pp = 0; pp < 2; pp++) {
                uint32_t bp[4];
                ldsm4(bp, bSh + (uint32_t)((we + pp * 16 + lrB) * 40 + kk + lcB) * 2);
                #pragma unroll
                for (int mt = 0; mt < 2; mt++) {
                    mma16(acc[mt][pp * 2], a[mt], bp);
                    mma16(acc[mt][pp * 2 + 1], a[mt], bp + 2);
                }
            }
        }
        if (it < 6)      { CP_WAIT(1); __syncthreads(); }
        else if (it < 7) { CP_WAIT(0); __syncthreads(); }
    }

    __half* Eo = g_Ewh + (size_t)w * MP2 * C_;
    #pragma unroll
    for (int mt = 0; mt < 2; mt++) {
        int m0r = mBase + wm + mt * 16 + gr;
        #pragma unroll
        for (int et = 0; et < 4; et++) {
            int e = eBase + we + et * 8 + 2 * gc;
            *(uint32_t*)&Eo[(size_t)m0r * C_ + e]       = pack2(acc[mt][et][0], acc[mt][et][1]);
            *(uint32_t*)&Eo[(size_t)(m0r + 8) * C_ + e] = pack2(acc[mt][et][2], acc[mt][et][3]);
        }
    }
}

// ---------------------------------------------------------------------------
// Fused attention (fp16 + ldmatrix + 3-stage ring): CTA = (window, 64 queries).
// ---------------------------------------------------------------------------
#define FA_SMEM_B (17408 + 3 * 8704 + 3 * 20480 + 5120 + 512)

__global__ __launch_bounds__(256, 2) void k_fattn()
{
    extern __shared__ __half fs[];
    __half* sTh  = fs;                    // [64][136]
    __half* sPhi = sTh + 64 * 136;        // [3][32][136]
    __half* sG   = sPhi + 3 * 32 * 136;   // [3][256][40]
    __half* sF   = sG + 3 * 256 * 40;     // [64][40]
    float*  sSum = (float*)(sF + 64 * 40);  // [64]
    float*  sInv = sSum + 64;               // [64]

    const int w = blockIdx.y, nBase = blockIdx.x * 64;
    const int b = w / 100, ih = (w / 10) % 10, iw = w % 10;
    const int tid = threadIdx.x, lane = tid & 31, wid = tid >> 5;
    const int gr = lane >> 2, gc = lane & 3;
    const int wn = (wid >> 1) * 16;     // n-range, both phases
    const int wmS = (wid & 1) * 16;     // S-phase m
    const int wcY = (wid & 1) * 128;    // Y-phase c
    const int lrA = lane & 15, lcA = (lane >> 4) * 8;
    const int lrB = (lane & 7) + ((lane >> 4) & 1) * 8, lcB = lane & 8;
    const __half* Eww = g_Ewh + (size_t)w * MP2 * C_;
    const __half* Xc  = g_Xc + (size_t)w * C_ * MP2;
    const float SC = 0.08838834764831843f;  // 1/sqrt(128)
    const uint32_t thB = (uint32_t)__cvta_generic_to_shared(sTh);
    const uint32_t phB = (uint32_t)__cvta_generic_to_shared(sPhi);
    const uint32_t gBB = (uint32_t)__cvta_generic_to_shared(sG);
    const uint32_t fB  = (uint32_t)__cvta_generic_to_shared(sF);

    if (tid < 64) sSum[tid] = 0.f;

    // theta once: sTh[n][e] (committed with group 0)
    #pragma unroll
    for (int l = 0; l < 4; l++) {
        int idx = tid + l * 256;
        int n = idx >> 4, ch = (idx & 15) * 8;
        cp16h(thB + (uint32_t)(n * 136 + ch) * 2, Eww + (size_t)(nBase + n) * C_ + ch);
    }

    auto issue = [&](int s, int m0) {
        #pragma unroll
        for (int l = 0; l < 2; l++) {
            int idx = tid + l * 256;
            int m = idx >> 4, ch = (idx & 15) * 8;
            cp16h(phB + (uint32_t)((s * 32 + m) * 136 + ch) * 2,
                  Eww + (size_t)(m0 + m) * C_ + CE + ch);
        }
        #pragma unroll
        for (int l = 0; l < 4; l++) {
            int idx = tid + l * 256;
            int c = idx >> 2, ch = (idx & 3) * 8;
            cp16h(gBB + (uint32_t)((s * 256 + c) * 40 + ch) * 2,
                  Xc + (size_t)c * MP2 + m0 + ch);
        }
        CP_COMMIT();
    };

    float yacc[16][4] = {};
    float colp[2] = {};

    issue(0, 0); issue(1, 32);
    CP_WAIT(1);
    __syncthreads();   // slot 0 ready; also covers sSum init

    for (int mi = 0; mi < 11; mi++) {
        int m0 = mi * 32;
        if (mi < 9) issue((mi + 2) % 3, (mi + 2) * 32);
        const uint32_t phSh = phB + (uint32_t)((mi % 3) * 32 * 136) * 2;
        const uint32_t gSh  = gBB + (uint32_t)((mi % 3) * 256 * 40) * 2;

        // S': A=theta[n][e], B=phi[m][e]
        float sacc[2][4] = {};
        #pragma unroll
        for (int ks = 0; ks < 8; ks++) {
            int kk = ks * 16;
            uint32_t a[4], bp[4];
            ldsm4(a, thB + (uint32_t)((wn + lrA) * 136 + kk + lcA) * 2);
            ldsm4(bp, phSh + (uint32_t)((wmS + lrB) * 136 + kk + lcB) * 2);
            mma16(sacc[0], a, bp);
            mma16(sacc[1], a, bp + 2);
        }
        // exp + mask + sF[n][m] + colsum partials
        #pragma unroll
        for (int t = 0; t < 2; t++) {
            int mg = m0 + wmS + t * 8 + 2 * gc;
            bool v = mg < NTOK;
            float e0 = v ? __expf(sacc[t][0] * SC) : 0.f;
            float e1 = v ? __expf(sacc[t][1] * SC) : 0.f;
            float e2 = v ? __expf(sacc[t][2] * SC) : 0.f;
            float e3 = v ? __expf(sacc[t][3] * SC) : 0.f;
            colp[0] += e0 + e1;
            colp[1] += e2 + e3;
            *(uint32_t*)&sF[(wn + gr) * 40 + wmS + t * 8 + 2 * gc]     = pack2(e0, e1);
            *(uint32_t*)&sF[(wn + gr + 8) * 40 + wmS + t * 8 + 2 * gc] = pack2(e2, e3);
        }
        __syncthreads();

        // Y': A=F'[n][m], B=G[c][m]
        #pragma unroll
        for (int ks = 0; ks < 2; ks++) {
            int kk = ks * 16;
            uint32_t a[4];
            ldsm4(a, fB + (uint32_t)((wn + lrA) * 40 + kk + lcA) * 2);
            #pragma unroll
            for (int pt = 0; pt < 8; pt++) {
                uint32_t bp[4];
                ldsm4(bp, gSh + (uint32_t)((wcY + pt * 16 + lrB) * 40 + kk + lcB) * 2);
                mma16(yacc[pt * 2], a, bp);
                mma16(yacc[pt * 2 + 1], a, bp + 2);
            }
        }
        if (mi < 9)       { CP_WAIT(1); __syncthreads(); }
        else if (mi < 10) { CP_WAIT(0); __syncthreads(); }
    }
    __syncthreads();   // sF/yacc reads done before colsum reuse of sSum

    // column sums (over m) per n
    colp[0] += __shfl_xor_sync(0xffffffffu, colp[0], 1);
    colp[0] += __shfl_xor_sync(0xffffffffu, colp[0], 2);
    colp[1] += __shfl_xor_sync(0xffffffffu, colp[1], 1);
    colp[1] += __shfl_xor_sync(0xffffffffu, colp[1], 2);
    if (gc == 0) {
        atomicAdd(&sSum[wn + gr], colp[0]);
        atomicAdd(&sSum[wn + gr + 8], colp[1]);
    }
    __syncthreads();
    if (tid < 64) sInv[tid] = 1.f / sSum[tid];
    __syncthreads();

    // scale + store Yh[b][hw][c]
    const int hwBase = ih * WS_ * W_ + iw * WS_;
    __half* Yb = g_Yh + (size_t)b * HW_ * C_;
    int n0 = nBase + wn + gr, n1 = n0 + 8;
    bool v0 = n0 < NTOK, v1 = n1 < NTOK;
    float i0 = sInv[wn + gr], i1 = sInv[wn + gr + 8];
    size_t r0 = v0 ? (size_t)(hwBase + (n0 / WS_) * W_ + n0 % WS_) * C_ : 0;
    size_t r1 = v1 ? (size_t)(hwBase + (n1 / WS_) * W_ + n1 % WS_) * C_ : 0;
    #pragma unroll
    for (int ct = 0; ct < 16; ct++) {
        int c = wcY + ct * 8 + 2 * gc;
        if (v0) *(uint32_t*)&Yb[r0 + c] = pack2(yacc[ct][0] * i0, yacc[ct][1] * i0);
        if (v1) *(uint32_t*)&Yb[r1 + c] = pack2(yacc[ct][2] * i1, yacc[ct][3] * i1);
    }
}

// ---------------------------------------------------------------------------
// pw1: out[o][p] = x + wproj[o][c] @ Yh[p][c]^T. BM=128 o, BN=64 p, K=256.
// 8 warps = 4(o) x 2(p): warp 32o x 32p (acc 32). occ 3.
// ---------------------------------------------------------------------------
#define PW1_SMEM ((3 * 128 * 40 + 3 * 64 * 40) * 2)

__global__ __launch_bounds__(256, 3) void k_pw1(
    const float* __restrict__ x, float* __restrict__ out)
{
    extern __shared__ __half qs[];
    __half* sA = qs;                    // [3][128][40]
    __half* sB = qs + 3 * 128 * 40;     // [3][64][40]
    const int b = blockIdx.z, oBase = blockIdx.y * 128, pBase = blockIdx.x * 64;
    const int tid = threadIdx.x, lane = tid & 31, wid = tid >> 5;
    const int wo = (wid >> 1) * 32, wp = (wid & 1) * 32;
    const int gr = lane >> 2, gc = lane & 3;
    const int lrA = lane & 15, lcA = (lane >> 4) * 8;
    const int lrB = (lane & 7) + ((lane >> 4) & 1) * 8, lcB = lane & 8;
    const __half* Yb = g_Yh + (size_t)b * HW_ * C_;
    const uint32_t aB = (uint32_t)__cvta_generic_to_shared(sA);
    const uint32_t bB = (uint32_t)__cvta_generic_to_shared(sB);

    auto issue = [&](int s, int k0) {
        #pragma unroll
        for (int l = 0; l < 2; l++) {
            int idx = tid + l * 256;
            int r = idx >> 2, ch = (idx & 3) * 8;
            cp16h(aB + (uint32_t)(s * 5120 + r * 40 + ch) * 2,
                  g_wh + (256 + oBase + r) * 256 + k0 + ch);
        }
        {
            int p = tid >> 2, ch = (tid & 3) * 8;
            int pg = pBase + p;
            bool v = pg < HW_;
            cp16p(bB + (uint32_t)(s * 2560 + p * 40 + ch) * 2,
                  Yb + (size_t)(v ? pg : 0) * C_ + k0 + ch, v);
        }
        CP_COMMIT();
    };

    float acc[2][4][4] = {};
    issue(0, 0); issue(1, 32);
    CP_WAIT(1);
    __syncthreads();
    for (int it = 0; it < 8; it++) {
        if (it < 6) issue((it + 2) % 3, (it + 2) * 32);
        const uint32_t aSh = aB + (uint32_t)((it % 3) * 5120) * 2;
        const uint32_t bSh = bB + (uint32_t)((it % 3) * 2560) * 2;
        #pragma unroll
        for (int ks = 0; ks < 2; ks++) {
            int kk = ks * 16;
            uint32_t a[2][4];
            #pragma unroll
            for (int ot = 0; ot < 2; ot++)
                ldsm4(a[ot], aSh + (uint32_t)((wo + ot * 16 + lrA) * 40 + kk + lcA) * 2);
            #pragma unroll
            for (int pp = 0; pp < 2; pp++) {
                uint32_t bp[4];
                ldsm4(bp, bSh + (uint32_t)((wp + pp * 16 + lrB) * 40 + kk + lcB) * 2);
                #pragma unroll
                for (int ot = 0; ot < 2; ot++) {
                    mma16(acc[ot][pp * 2], a[ot], bp);
                    mma16(acc[ot][pp * 2 + 1], a[ot], bp + 2);
                }
            }
        }
        if (it < 6)      { CP_WAIT(1); __syncthreads(); }
        else if (it < 7) { CP_WAIT(0); __syncthreads(); }
    }

    #pragma unroll
    for (int ot = 0; ot < 2; ot++) {
        int o0 = oBase + wo + ot * 16 + gr;
        size_t row0 = ((size_t)b * C_ + o0) * HW_;
        size_t row1 = ((size_t)b * C_ + o0 + 8) * HW_;
        #pragma unroll
        for (int pt = 0; pt < 4; pt++) {
            int p = pBase + wp + pt * 8 + 2 * gc;
            if (p < HW_) {
                float2 r0 = *(const float2*)&x[row0 + p];
                float2 r1 = *(const float2*)&x[row1 + p];
                *(float2*)&out[row0 + p] =
                    make_float2(acc[ot][pt][0] + r0.x, acc[ot][pt][1] + r0.y);
                *(float2*)&out[row1 + p] =
                    make_float2(acc[ot][pt][2] + r1.x, acc[ot][pt][3] + r1.y);
            }
        }
    }
}

// ---------------------------------------------------------------------------
extern "C" void kernel_launch(void* const* d_in, const int* in_sizes, int n_in,
                              void* d_out, int out_size)
{
    const float* x       = (const float*)d_in[0];
    const float* w_theta = (const float*)d_in[1];
    const float* w_phi   = (const float*)d_in[2];
    const float* w_proj  = (const float*)d_in[3];
    float* out = (float*)d_out;

    cudaFuncSetAttribute(k_pw0, cudaFuncAttributeMaxDynamicSharedMemorySize, PW0_SMEM);
    cudaFuncSetAttribute(k_fattn, cudaFuncAttributeMaxDynamicSharedMemorySize, FA_SMEM_B);
    cudaFuncSetAttribute(k_pw1, cudaFuncAttributeMaxDynamicSharedMemorySize, PW1_SMEM);

    // 1) convert x (two layouts) + weights to half
    k_prep<<<NWIN + 4, 256>>>(x, w_theta, w_phi, w_proj);
    // 2) embeddings -> Ewh[w][m][chan]
    dim3 g0(6, 2, NWIN);
    k_pw0<<<g0, 256, PW0_SMEM>>>();
    // 3) fused attention -> Yh[b][hw][c]
    dim3 gf(6, NWIN);
    k_fattn<<<gf, 256, FA_SMEM_B>>>();
    // 4) out = x + w_proj @ Y
    dim3 g1((HW_ + 63) / 64, 2, B_);   // (507, 2, 4)
    k_pw1<<<g1, 256, PW1_SMEM>>>(x, out);
}